// round 1
// baseline (speedup 1.0000x reference)
#include <cuda_runtime.h>

// ---------------------------------------------------------------------------
// Transformer block with RBF x spherical-harmonic relative-position encoding.
// Key algebraic optimization: never materialize rp[B,L,L,576] @ rp_w (77 GFLOP).
// Instead fold q into rp_w once:  vw[b,l,h,f] = sum_dh rp_w[f,h*64+dh]*q[b,l,h,dh]
// then rp_scores = env * sum_s sph_s * sum_r rbf_r * vw[...,s*64+r] + cb.
// Total work drops to ~4 GFLOP fp32.
// ---------------------------------------------------------------------------

#define CUTOFF  10.0f
#define NRAD    64
#define NSPH    9
#define NHEADS  8
#define DMODEL  512
#define DHEAD   64
#define SEQL    256
#define NB      2
#define NROWS   (NB*SEQL)      // 512
#define NF      (NRAD*NSPH)    // 576
#define DFF     2048
#define KSPLIT  4

// Scratch (static device globals; no runtime allocation allowed)
__device__ __align__(16) float g_vw[NROWS*NHEADS*NF];          // 9.4 MB [row][h][f]
__device__ __align__(16) float g_cb[NROWS*NHEADS];
__device__ __align__(16) float g_base[NB*NHEADS*SEQL*SEQL];    // 4 MB  [b][h][l][m]
__device__ __align__(16) float g_x1[NROWS*DMODEL];             // post-LN1 x
__device__ __align__(16) float g_hid[NROWS*DFF];               // FFN hidden
__device__ __align__(16) float g_yp[KSPLIT*NROWS*DMODEL];      // GEMM2 split-K partials

// ---------------------------------------------------------------------------
// K1: vw[row, h, f] = sum_dh src[row, h*64+dh] * rp_w[f, h*64+dh]
// 64x64 tile per block, K=64 resident in smem, 4x4 microtile per thread.
// grid: (9 f-tiles, 8 row-tiles, 8 heads)
// ---------------------------------------------------------------------------
__global__ __launch_bounds__(256) void k_vw(const float* __restrict__ src,
                                            const float* __restrict__ rp_w) {
    __shared__ __align__(16) float As[64][64];   // [dh][row]
    __shared__ __align__(16) float Bs[64][64];   // [dh][f]
    const int f0   = blockIdx.x * 64;
    const int row0 = blockIdx.y * 64;
    const int h    = blockIdx.z;
    const int tid  = threadIdx.x;
#pragma unroll
    for (int i = 0; i < 4; i++) {
        int lin = i * 256 + tid;            // 0..1023
        int r   = lin >> 4;                 // 0..63
        int k4  = lin & 15;                 // 0..15 (float4 group along dh)
        float4 a = *(const float4*)&src [(row0 + r) * DMODEL + h * DHEAD + k4 * 4];
        As[k4*4+0][r] = a.x; As[k4*4+1][r] = a.y; As[k4*4+2][r] = a.z; As[k4*4+3][r] = a.w;
        float4 b = *(const float4*)&rp_w[(f0   + r) * DMODEL + h * DHEAD + k4 * 4];
        Bs[k4*4+0][r] = b.x; Bs[k4*4+1][r] = b.y; Bs[k4*4+2][r] = b.z; Bs[k4*4+3][r] = b.w;
    }
    __syncthreads();
    const int tx = tid & 15, ty = tid >> 4;
    float acc[4][4] = {};
#pragma unroll
    for (int k = 0; k < 64; k++) {
        float a[4], b[4];
        *(float4*)a = *(const float4*)&As[k][ty * 4];
        *(float4*)b = *(const float4*)&Bs[k][tx * 4];
#pragma unroll
        for (int i = 0; i < 4; i++)
#pragma unroll
            for (int j = 0; j < 4; j++) acc[i][j] += a[i] * b[j];
    }
#pragma unroll
    for (int i = 0; i < 4; i++) {
        float4 o = make_float4(acc[i][0], acc[i][1], acc[i][2], acc[i][3]);
        *(float4*)&g_vw[(row0 + ty*4 + i) * (NHEADS*NF) + h * NF + f0 + tx * 4] = o;
    }
}

// ---------------------------------------------------------------------------
// K1b: cb[row,h] = sum_dh rp_b[h*64+dh]*src[row, h*64+dh]  (m-independent bias)
// ---------------------------------------------------------------------------
__global__ void k_cb(const float* __restrict__ src, const float* __restrict__ rp_b) {
    int i = blockIdx.x * blockDim.x + threadIdx.x;
    if (i >= NROWS * NHEADS) return;
    int row = i >> 3, h = i & 7;
    const float* s  = &src[row * DMODEL + h * DHEAD];
    const float* bb = &rp_b[h * DHEAD];
    float acc = 0.0f;
#pragma unroll
    for (int k = 0; k < DHEAD; k++) acc += s[k] * bb[k];
    g_cb[i] = acc;
}

// ---------------------------------------------------------------------------
// K2: base[b,h,l,m] = (1/8) * sum_dh q[b,l,h,dh]*q[b,m,h,dh]
// grid: (4 m-tiles, 4 l-tiles, 16 = b*8+h)
// ---------------------------------------------------------------------------
__global__ __launch_bounds__(256) void k_base(const float* __restrict__ src) {
    __shared__ __align__(16) float As[64][64];   // [dh][l]
    __shared__ __align__(16) float Bs[64][64];   // [dh][m]
    const int m0 = blockIdx.x * 64;
    const int l0 = blockIdx.y * 64;
    const int b  = blockIdx.z >> 3;
    const int h  = blockIdx.z & 7;
    const int tid = threadIdx.x;
    const float* sb = src + b * SEQL * DMODEL;
#pragma unroll
    for (int i = 0; i < 4; i++) {
        int lin = i * 256 + tid;
        int r   = lin >> 4;
        int k4  = lin & 15;
        float4 a = *(const float4*)&sb[(l0 + r) * DMODEL + h * DHEAD + k4 * 4];
        As[k4*4+0][r] = a.x; As[k4*4+1][r] = a.y; As[k4*4+2][r] = a.z; As[k4*4+3][r] = a.w;
        float4 c = *(const float4*)&sb[(m0 + r) * DMODEL + h * DHEAD + k4 * 4];
        Bs[k4*4+0][r] = c.x; Bs[k4*4+1][r] = c.y; Bs[k4*4+2][r] = c.z; Bs[k4*4+3][r] = c.w;
    }
    __syncthreads();
    const int tx = tid & 15, ty = tid >> 4;
    float acc[4][4] = {};
#pragma unroll
    for (int k = 0; k < 64; k++) {
        float a[4], c[4];
        *(float4*)a = *(const float4*)&As[k][ty * 4];
        *(float4*)c = *(const float4*)&Bs[k][tx * 4];
#pragma unroll
        for (int i = 0; i < 4; i++)
#pragma unroll
            for (int j = 0; j < 4; j++) acc[i][j] += a[i] * c[j];
    }
#pragma unroll
    for (int i = 0; i < 4; i++) {
        float4 o = make_float4(acc[i][0]*0.125f, acc[i][1]*0.125f,
                               acc[i][2]*0.125f, acc[i][3]*0.125f);
        *(float4*)&g_base[((b*NHEADS + h)*SEQL + l0 + ty*4 + i) * SEQL + m0 + tx*4] = o;
    }
}

// ---------------------------------------------------------------------------
// K3: fused per-(b,l) block: rbf/sph scores + softmax + attn@V + residual + LN1
// 256 threads; thread tid owns key position m=tid (scores) then dims tid,tid+256.
// ---------------------------------------------------------------------------
__global__ __launch_bounds__(256) void k_attn(
    const float* __restrict__ src, const float* __restrict__ rel_diss,
    const float* __restrict__ rel_dirs, const float* __restrict__ gamma1,
    const float* __restrict__ beta1) {
    __shared__ __align__(16) float vw_sm[NHEADS * NF];   // 18 KB
    __shared__ float w_sm[NHEADS * SEQL];                // logits -> weights, 8 KB
    __shared__ float cb_sm[NHEADS];
    __shared__ float maxv[NHEADS], sumv[NHEADS];
    __shared__ float redA[256], redB[256];

    const int row = blockIdx.x;        // b*256 + l
    const int b   = row >> 8;
    const int l   = row & 255;
    const int tid = threadIdx.x;

    {   // stage vw for this (b,l) into smem (broadcast-reused by all 256 m's)
        const float4* vs = (const float4*)&g_vw[row * (NHEADS * NF)];
        float4* vd = (float4*)vw_sm;
        for (int i = tid; i < (NHEADS * NF) / 4; i += 256) vd[i] = vs[i];
        if (tid < NHEADS) cb_sm[tid] = g_cb[row * NHEADS + tid];
    }
    __syncthreads();

    // ---- per-m edge features + 72-way contraction -------------------------
    const int m = tid;
    const float d  = rel_diss[row * SEQL + m];
    const float dx = rel_dirs[(row * SEQL + m) * 3 + 0];
    const float dy = rel_dirs[(row * SEQL + m) * 3 + 1];
    const float dz = rel_dirs[(row * SEQL + m) * 3 + 2];
    const float dc  = fminf(fmaxf(d * (1.0f / CUTOFF), 0.0f), 1.0f);
    const float env = 0.5f * (__cosf(3.14159265358979f * dc) + 1.0f);

    float t[NHEADS * NSPH];
#pragma unroll
    for (int u = 0; u < NHEADS * NSPH; u++) t[u] = 0.0f;

    const float inv2w2 = 20.48f;                  // 1/(2*(CUTOFF/NRAD)^2)
    const float cstep  = CUTOFF / 63.0f;          // linspace(0,10,64) step
#pragma unroll 2
    for (int r4 = 0; r4 < NRAD / 4; r4++) {
        float g[4];
#pragma unroll
        for (int q = 0; q < 4; q++) {
            float diff = d - (float)(r4 * 4 + q) * cstep;
            g[q] = __expf(-diff * diff * inv2w2);
        }
#pragma unroll
        for (int h = 0; h < NHEADS; h++)
#pragma unroll
            for (int s = 0; s < NSPH; s++) {
                float4 v = *(const float4*)&vw_sm[h * NF + s * NRAD + r4 * 4];
                float acc = t[h * NSPH + s];
                acc += g[0] * v.x; acc += g[1] * v.y;
                acc += g[2] * v.z; acc += g[3] * v.w;
                t[h * NSPH + s] = acc;
            }
    }

    // real spherical harmonics l<=2 (reference order)
    float sp[9];
    sp[0] = 0.28209479177387814f;
    sp[1] = 0.4886025119029199f * dy;
    sp[2] = 0.4886025119029199f * dz;
    sp[3] = 0.4886025119029199f * dx;
    sp[4] = 1.0925484305920792f * dx * dy;
    sp[5] = 1.0925484305920792f * dy * dz;
    sp[6] = 0.31539156525252005f * (3.0f * dz * dz - 1.0f);
    sp[7] = 1.0925484305920792f * dx * dz;
    sp[8] = 0.5462742152960396f * (dx * dx - dy * dy);

#pragma unroll
    for (int h = 0; h < NHEADS; h++) {
        float rp = 0.0f;
#pragma unroll
        for (int s = 0; s < NSPH; s++) rp += sp[s] * t[h * NSPH + s];
        float logit = g_base[((b * NHEADS + h) * SEQL + l) * SEQL + m]
                    + env * rp + cb_sm[h];
        w_sm[h * SEQL + m] = logit;
    }
    __syncthreads();

    // ---- softmax over m (warp w reduces head h=w) -------------------------
    const int wrp = tid >> 5, lane = tid & 31;
    {
        float mv = -1e30f;
#pragma unroll
        for (int i = 0; i < 8; i++) mv = fmaxf(mv, w_sm[wrp * SEQL + lane + i * 32]);
#pragma unroll
        for (int o = 16; o > 0; o >>= 1) mv = fmaxf(mv, __shfl_xor_sync(0xffffffffu, mv, o));
        if (lane == 0) maxv[wrp] = mv;
    }
    __syncthreads();
#pragma unroll
    for (int h = 0; h < NHEADS; h++)
        w_sm[h * SEQL + tid] = __expf(w_sm[h * SEQL + tid] - maxv[h]);
    __syncthreads();
    {
        float sv = 0.0f;
#pragma unroll
        for (int i = 0; i < 8; i++) sv += w_sm[wrp * SEQL + lane + i * 32];
#pragma unroll
        for (int o = 16; o > 0; o >>= 1) sv += __shfl_xor_sync(0xffffffffu, sv, o);
        if (lane == 0) sumv[wrp] = sv;
    }
    __syncthreads();

    // ---- attn @ V (V = src), residual, LN1 --------------------------------
    const int d0 = tid, d1 = tid + 256;
    const int h0 = tid >> 6, h1 = 4 + h0;
    const float* sb = src + b * SEQL * DMODEL;
    float acc0 = 0.0f, acc1 = 0.0f;
#pragma unroll 4
    for (int mm = 0; mm < SEQL; mm++) {
        float wa = w_sm[h0 * SEQL + mm];
        float wb = w_sm[h1 * SEQL + mm];
        acc0 += wa * sb[mm * DMODEL + d0];
        acc1 += wb * sb[mm * DMODEL + d1];
    }
    float x0 = src[row * DMODEL + d0] + acc0 / sumv[h0];
    float x1 = src[row * DMODEL + d1] + acc1 / sumv[h1];

    redA[tid] = x0 + x1;
    redB[tid] = x0 * x0 + x1 * x1;
    __syncthreads();
    for (int st = 128; st > 0; st >>= 1) {
        if (tid < st) { redA[tid] += redA[tid + st]; redB[tid] += redB[tid + st]; }
        __syncthreads();
    }
    const float mu   = redA[0] * (1.0f / DMODEL);
    const float var  = redB[0] * (1.0f / DMODEL) - mu * mu;
    const float rstd = rsqrtf(var + 1e-5f);
    g_x1[row * DMODEL + d0] = (x0 - mu) * rstd * gamma1[d0] + beta1[d0];
    g_x1[row * DMODEL + d1] = (x1 - mu) * rstd * gamma1[d1] + beta1[d1];
}

// ---------------------------------------------------------------------------
// K4: FFN GEMM1  g_hid = leaky_relu(g_x1 @ w1 + b1)
// 64x64 tiles, K-chunks of 16. grid: (32 col-tiles, 8 row-tiles)
// ---------------------------------------------------------------------------
__global__ __launch_bounds__(256) void k_gemm1(const float* __restrict__ w1,
                                               const float* __restrict__ b1) {
    __shared__ __align__(16) float As[16][64];   // [k][row]
    __shared__ __align__(16) float Bs[16][64];   // [k][col]
    const int col0 = blockIdx.x * 64;
    const int row0 = blockIdx.y * 64;
    const int tid  = threadIdx.x;
    const int tx = tid & 15, ty = tid >> 4;
    float acc[4][4] = {};
    for (int k0 = 0; k0 < DMODEL; k0 += 16) {
        {
            int r = tid >> 2, kg = tid & 3;
            float4 v = *(const float4*)&g_x1[(row0 + r) * DMODEL + k0 + kg * 4];
            As[kg*4+0][r] = v.x; As[kg*4+1][r] = v.y; As[kg*4+2][r] = v.z; As[kg*4+3][r] = v.w;
        }
        {
            int k = tid >> 4, cg = tid & 15;
            float4 v = *(const float4*)&w1[(k0 + k) * DFF + col0 + cg * 4];
            *(float4*)&Bs[k][cg * 4] = v;
        }
        __syncthreads();
#pragma unroll
        for (int k = 0; k < 16; k++) {
            float a[4], c[4];
            *(float4*)a = *(const float4*)&As[k][ty * 4];
            *(float4*)c = *(const float4*)&Bs[k][tx * 4];
#pragma unroll
            for (int i = 0; i < 4; i++)
#pragma unroll
                for (int j = 0; j < 4; j++) acc[i][j] += a[i] * c[j];
        }
        __syncthreads();
    }
#pragma unroll
    for (int i = 0; i < 4; i++) {
        float4 o;
        float v0 = acc[i][0] + b1[col0 + tx*4 + 0];
        float v1 = acc[i][1] + b1[col0 + tx*4 + 1];
        float v2 = acc[i][2] + b1[col0 + tx*4 + 2];
        float v3 = acc[i][3] + b1[col0 + tx*4 + 3];
        o.x = v0 > 0.0f ? v0 : 0.01f * v0;
        o.y = v1 > 0.0f ? v1 : 0.01f * v1;
        o.z = v2 > 0.0f ? v2 : 0.01f * v2;
        o.w = v3 > 0.0f ? v3 : 0.01f * v3;
        *(float4*)&g_hid[(row0 + ty*4 + i) * DFF + col0 + tx * 4] = o;
    }
}

// ---------------------------------------------------------------------------
// K5: FFN GEMM2 (split-K, deterministic partials)  g_yp[kz] = g_hid @ w2 (K slice)
// grid: (8 col-tiles, 8 row-tiles, KSPLIT)
// ---------------------------------------------------------------------------
__global__ __launch_bounds__(256) void k_gemm2(const float* __restrict__ w2) {
    __shared__ __align__(16) float As[16][64];   // [k][row]
    __shared__ __align__(16) float Bs[16][64];   // [k][col]
    const int col0 = blockIdx.x * 64;
    const int row0 = blockIdx.y * 64;
    const int kz   = blockIdx.z;
    const int tid  = threadIdx.x;
    const int tx = tid & 15, ty = tid >> 4;
    const int kbeg = kz * (DFF / KSPLIT);
    float acc[4][4] = {};
    for (int kc = 0; kc < DFF / KSPLIT; kc += 16) {
        int k0 = kbeg + kc;
        {
            int r = tid >> 2, kg = tid & 3;
            float4 v = *(const float4*)&g_hid[(row0 + r) * DFF + k0 + kg * 4];
            As[kg*4+0][r] = v.x; As[kg*4+1][r] = v.y; As[kg*4+2][r] = v.z; As[kg*4+3][r] = v.w;
        }
        {
            int k = tid >> 4, cg = tid & 15;
            float4 v = *(const float4*)&w2[(k0 + k) * DMODEL + col0 + cg * 4];
            *(float4*)&Bs[k][cg * 4] = v;
        }
        __syncthreads();
#pragma unroll
        for (int k = 0; k < 16; k++) {
            float a[4], c[4];
            *(float4*)a = *(const float4*)&As[k][ty * 4];
            *(float4*)c = *(const float4*)&Bs[k][tx * 4];
#pragma unroll
            for (int i = 0; i < 4; i++)
#pragma unroll
                for (int j = 0; j < 4; j++) acc[i][j] += a[i] * c[j];
        }
        __syncthreads();
    }
#pragma unroll
    for (int i = 0; i < 4; i++) {
        float4 o = make_float4(acc[i][0], acc[i][1], acc[i][2], acc[i][3]);
        *(float4*)&g_yp[kz * NROWS * DMODEL + (row0 + ty*4 + i) * DMODEL + col0 + tx * 4] = o;
    }
}

// ---------------------------------------------------------------------------
// K6: combine split-K partials + b2 + residual(x) -> LN2 -> out
// ---------------------------------------------------------------------------
__global__ __launch_bounds__(256) void k_ln2(const float* __restrict__ b2,
                                             const float* __restrict__ gamma2,
                                             const float* __restrict__ beta2,
                                             float* __restrict__ out) {
    __shared__ float redA[256], redB[256];
    const int row = blockIdx.x;
    const int tid = threadIdx.x;
    const int d0 = tid, d1 = tid + 256;
    float y0 = g_x1[row * DMODEL + d0] + b2[d0];
    float y1 = g_x1[row * DMODEL + d1] + b2[d1];
#pragma unroll
    for (int kz = 0; kz < KSPLIT; kz++) {
        y0 += g_yp[kz * NROWS * DMODEL + row * DMODEL + d0];
        y1 += g_yp[kz * NROWS * DMODEL + row * DMODEL + d1];
    }
    redA[tid] = y0 + y1;
    redB[tid] = y0 * y0 + y1 * y1;
    __syncthreads();
    for (int st = 128; st > 0; st >>= 1) {
        if (tid < st) { redA[tid] += redA[tid + st]; redB[tid] += redB[tid + st]; }
        __syncthreads();
    }
    const float mu   = redA[0] * (1.0f / DMODEL);
    const float var  = redB[0] * (1.0f / DMODEL) - mu * mu;
    const float rstd = rsqrtf(var + 1e-5f);
    out[row * DMODEL + d0] = (y0 - mu) * rstd * gamma2[d0] + beta2[d0];
    out[row * DMODEL + d1] = (y1 - mu) * rstd * gamma2[d1] + beta2[d1];
}

// ---------------------------------------------------------------------------
extern "C" void kernel_launch(void* const* d_in, const int* in_sizes, int n_in,
                              void* d_out, int out_size) {
    (void)in_sizes; (void)n_in; (void)out_size;
    const float* src      = (const float*)d_in[0];
    const float* rel_diss = (const float*)d_in[1];
    const float* rel_dirs = (const float*)d_in[2];
    const float* rp_w     = (const float*)d_in[3];
    const float* rp_b     = (const float*)d_in[4];
    const float* w1       = (const float*)d_in[5];
    const float* b1       = (const float*)d_in[6];
    const float* w2       = (const float*)d_in[7];
    const float* b2       = (const float*)d_in[8];
    const float* gamma1   = (const float*)d_in[9];
    const float* beta1    = (const float*)d_in[10];
    const float* gamma2   = (const float*)d_in[11];
    const float* beta2    = (const float*)d_in[12];
    float* out = (float*)d_out;

    k_vw   <<<dim3(NF/64, NROWS/64, NHEADS), 256>>>(src, rp_w);
    k_cb   <<<(NROWS*NHEADS + 255)/256, 256>>>(src, rp_b);
    k_base <<<dim3(SEQL/64, SEQL/64, NB*NHEADS), 256>>>(src);
    k_attn <<<NROWS, 256>>>(src, rel_diss, rel_dirs, gamma1, beta1);
    k_gemm1<<<dim3(DFF/64, NROWS/64), 256>>>(w1, b1);
    k_gemm2<<<dim3(DMODEL/64, NROWS/64, KSPLIT), 256>>>(w2);
    k_ln2  <<<NROWS, 256>>>(b2, gamma2, beta2, out);
}

// round 2
// speedup vs baseline: 1.1582x; 1.1582x over previous
#include <cuda_runtime.h>

// ---------------------------------------------------------------------------
// Transformer block with RBF x spherical-harmonic relative-position encoding.
// rp path factorized: vw[b,l,h,f] = sum_dh rp_w[f,h*64+dh]*q[b,l,h,dh], then
// rp_scores = env * sum_r g[r] * (sum_s sph_s * vw[...,s*64+r]) + cb.
// R1->R2: k_attn contraction reordered (r outer, h inner) to cut per-thread
// accumulator state 72 -> 8+9, raising occupancy; AV loop float2-vectorized.
// ---------------------------------------------------------------------------

#define CUTOFF  10.0f
#define NRAD    64
#define NSPH    9
#define NHEADS  8
#define DMODEL  512
#define DHEAD   64
#define SEQL    256
#define NB      2
#define NROWS   (NB*SEQL)      // 512
#define NF      (NRAD*NSPH)    // 576
#define DFF     2048
#define KSPLIT  4

__device__ __align__(16) float g_vw[NROWS*NHEADS*NF];          // [row][h][f]
__device__ __align__(16) float g_cb[NROWS*NHEADS];
__device__ __align__(16) float g_base[NB*NHEADS*SEQL*SEQL];    // [b][h][l][m]
__device__ __align__(16) float g_x1[NROWS*DMODEL];
__device__ __align__(16) float g_hid[NROWS*DFF];
__device__ __align__(16) float g_yp[KSPLIT*NROWS*DMODEL];

// ---------------------------------------------------------------------------
// K1: vw[row, h, f] = sum_dh src[row, h*64+dh] * rp_w[f, h*64+dh]
// ---------------------------------------------------------------------------
__global__ __launch_bounds__(256) void k_vw(const float* __restrict__ src,
                                            const float* __restrict__ rp_w) {
    __shared__ __align__(16) float As[64][64];   // [dh][row]
    __shared__ __align__(16) float Bs[64][64];   // [dh][f]
    const int f0   = blockIdx.x * 64;
    const int row0 = blockIdx.y * 64;
    const int h    = blockIdx.z;
    const int tid  = threadIdx.x;
#pragma unroll
    for (int i = 0; i < 4; i++) {
        int lin = i * 256 + tid;
        int r   = lin >> 4;
        int k4  = lin & 15;
        float4 a = *(const float4*)&src [(row0 + r) * DMODEL + h * DHEAD + k4 * 4];
        As[k4*4+0][r] = a.x; As[k4*4+1][r] = a.y; As[k4*4+2][r] = a.z; As[k4*4+3][r] = a.w;
        float4 b = *(const float4*)&rp_w[(f0   + r) * DMODEL + h * DHEAD + k4 * 4];
        Bs[k4*4+0][r] = b.x; Bs[k4*4+1][r] = b.y; Bs[k4*4+2][r] = b.z; Bs[k4*4+3][r] = b.w;
    }
    __syncthreads();
    const int tx = tid & 15, ty = tid >> 4;
    float acc[4][4] = {};
#pragma unroll
    for (int k = 0; k < 64; k++) {
        float a[4], b[4];
        *(float4*)a = *(const float4*)&As[k][ty * 4];
        *(float4*)b = *(const float4*)&Bs[k][tx * 4];
#pragma unroll
        for (int i = 0; i < 4; i++)
#pragma unroll
            for (int j = 0; j < 4; j++) acc[i][j] += a[i] * b[j];
    }
#pragma unroll
    for (int i = 0; i < 4; i++) {
        float4 o = make_float4(acc[i][0], acc[i][1], acc[i][2], acc[i][3]);
        *(float4*)&g_vw[(row0 + ty*4 + i) * (NHEADS*NF) + h * NF + f0 + tx * 4] = o;
    }
}

// ---------------------------------------------------------------------------
// K1b: cb[row,h] = sum_dh rp_b[h*64+dh]*src[row, h*64+dh]
// ---------------------------------------------------------------------------
__global__ void k_cb(const float* __restrict__ src, const float* __restrict__ rp_b) {
    int i = blockIdx.x * blockDim.x + threadIdx.x;
    if (i >= NROWS * NHEADS) return;
    int row = i >> 3, h = i & 7;
    const float* s  = &src[row * DMODEL + h * DHEAD];
    const float* bb = &rp_b[h * DHEAD];
    float acc = 0.0f;
#pragma unroll
    for (int k = 0; k < DHEAD; k++) acc += s[k] * bb[k];
    g_cb[i] = acc;
}

// ---------------------------------------------------------------------------
// K2: base[b,h,l,m] = (1/8) * sum_dh q[b,l,h,dh]*q[b,m,h,dh]
// ---------------------------------------------------------------------------
__global__ __launch_bounds__(256) void k_base(const float* __restrict__ src) {
    __shared__ __align__(16) float As[64][64];
    __shared__ __align__(16) float Bs[64][64];
    const int m0 = blockIdx.x * 64;
    const int l0 = blockIdx.y * 64;
    const int b  = blockIdx.z >> 3;
    const int h  = blockIdx.z & 7;
    const int tid = threadIdx.x;
    const float* sb = src + b * SEQL * DMODEL;
#pragma unroll
    for (int i = 0; i < 4; i++) {
        int lin = i * 256 + tid;
        int r   = lin >> 4;
        int k4  = lin & 15;
        float4 a = *(const float4*)&sb[(l0 + r) * DMODEL + h * DHEAD + k4 * 4];
        As[k4*4+0][r] = a.x; As[k4*4+1][r] = a.y; As[k4*4+2][r] = a.z; As[k4*4+3][r] = a.w;
        float4 c = *(const float4*)&sb[(m0 + r) * DMODEL + h * DHEAD + k4 * 4];
        Bs[k4*4+0][r] = c.x; Bs[k4*4+1][r] = c.y; Bs[k4*4+2][r] = c.z; Bs[k4*4+3][r] = c.w;
    }
    __syncthreads();
    const int tx = tid & 15, ty = tid >> 4;
    float acc[4][4] = {};
#pragma unroll
    for (int k = 0; k < 64; k++) {
        float a[4], c[4];
        *(float4*)a = *(const float4*)&As[k][ty * 4];
        *(float4*)c = *(const float4*)&Bs[k][tx * 4];
#pragma unroll
        for (int i = 0; i < 4; i++)
#pragma unroll
            for (int j = 0; j < 4; j++) acc[i][j] += a[i] * c[j];
    }
#pragma unroll
    for (int i = 0; i < 4; i++) {
        float4 o = make_float4(acc[i][0]*0.125f, acc[i][1]*0.125f,
                               acc[i][2]*0.125f, acc[i][3]*0.125f);
        *(float4*)&g_base[((b*NHEADS + h)*SEQL + l0 + ty*4 + i) * SEQL + m0 + tx*4] = o;
    }
}

// ---------------------------------------------------------------------------
// K3: fused per-(b,l): rp scores + softmax + attn@V + residual + LN1.
// Contraction reordered: r4 outer, h inner -> tiny accumulator state (rp[8]).
// ---------------------------------------------------------------------------
__global__ __launch_bounds__(256, 2) void k_attn(
    const float* __restrict__ src, const float* __restrict__ rel_diss,
    const float* __restrict__ rel_dirs, const float* __restrict__ gamma1,
    const float* __restrict__ beta1) {
    __shared__ __align__(16) float vw_sm[NHEADS * NF];   // 18 KB
    __shared__ float w_sm[NHEADS * SEQL];                // 8 KB
    __shared__ float cb_sm[NHEADS];
    __shared__ float maxv[NHEADS], sumv[NHEADS];
    __shared__ float redA[256], redB[256];

    const int row = blockIdx.x;        // b*256 + l
    const int b   = row >> 8;
    const int l   = row & 255;
    const int tid = threadIdx.x;

    {   // stage vw for this (b,l) into smem
        const float4* vs = (const float4*)&g_vw[row * (NHEADS * NF)];
        float4* vd = (float4*)vw_sm;
        for (int i = tid; i < (NHEADS * NF) / 4; i += 256) vd[i] = vs[i];
        if (tid < NHEADS) cb_sm[tid] = g_cb[row * NHEADS + tid];
    }
    __syncthreads();

    // ---- per-m edge features + contraction --------------------------------
    const int m = tid;
    const float d  = rel_diss[row * SEQL + m];
    const float dx = rel_dirs[(row * SEQL + m) * 3 + 0];
    const float dy = rel_dirs[(row * SEQL + m) * 3 + 1];
    const float dz = rel_dirs[(row * SEQL + m) * 3 + 2];
    const float dc  = fminf(fmaxf(d * (1.0f / CUTOFF), 0.0f), 1.0f);
    const float env = 0.5f * (__cosf(3.14159265358979f * dc) + 1.0f);

    float sp[9];
    sp[0] = 0.28209479177387814f;
    sp[1] = 0.4886025119029199f * dy;
    sp[2] = 0.4886025119029199f * dz;
    sp[3] = 0.4886025119029199f * dx;
    sp[4] = 1.0925484305920792f * dx * dy;
    sp[5] = 1.0925484305920792f * dy * dz;
    sp[6] = 0.31539156525252005f * (3.0f * dz * dz - 1.0f);
    sp[7] = 1.0925484305920792f * dx * dz;
    sp[8] = 0.5462742152960396f * (dx * dx - dy * dy);

    float rp[NHEADS];
#pragma unroll
    for (int h = 0; h < NHEADS; h++) rp[h] = 0.0f;

    const float inv2w2 = 20.48f;                  // 1/(2*(CUTOFF/NRAD)^2)
    const float cstep  = CUTOFF / 63.0f;          // linspace(0,10,64) step
#pragma unroll 2
    for (int r4 = 0; r4 < NRAD / 4; r4++) {
        float g0, g1, g2, g3;
        {
            float f0 = d - (float)(r4 * 4 + 0) * cstep;
            float f1 = d - (float)(r4 * 4 + 1) * cstep;
            float f2 = d - (float)(r4 * 4 + 2) * cstep;
            float f3 = d - (float)(r4 * 4 + 3) * cstep;
            g0 = __expf(-f0 * f0 * inv2w2);
            g1 = __expf(-f1 * f1 * inv2w2);
            g2 = __expf(-f2 * f2 * inv2w2);
            g3 = __expf(-f3 * f3 * inv2w2);
        }
#pragma unroll
        for (int h = 0; h < NHEADS; h++) {
            float ux = 0.0f, uy = 0.0f, uz = 0.0f, uw = 0.0f;
#pragma unroll
            for (int s = 0; s < NSPH; s++) {
                float4 v = *(const float4*)&vw_sm[h * NF + s * NRAD + r4 * 4];
                ux += sp[s] * v.x; uy += sp[s] * v.y;
                uz += sp[s] * v.z; uw += sp[s] * v.w;
            }
            rp[h] += g0 * ux + g1 * uy + g2 * uz + g3 * uw;
        }
    }

#pragma unroll
    for (int h = 0; h < NHEADS; h++) {
        w_sm[h * SEQL + m] = g_base[((b * NHEADS + h) * SEQL + l) * SEQL + m]
                           + env * rp[h] + cb_sm[h];
    }
    __syncthreads();

    // ---- softmax over m (warp w reduces head h=w) -------------------------
    const int wrp = tid >> 5, lane = tid & 31;
    {
        float mv = -1e30f;
#pragma unroll
        for (int i = 0; i < 8; i++) mv = fmaxf(mv, w_sm[wrp * SEQL + lane + i * 32]);
#pragma unroll
        for (int o = 16; o > 0; o >>= 1) mv = fmaxf(mv, __shfl_xor_sync(0xffffffffu, mv, o));
        if (lane == 0) maxv[wrp] = mv;
    }
    __syncthreads();
#pragma unroll
    for (int h = 0; h < NHEADS; h++)
        w_sm[h * SEQL + tid] = __expf(w_sm[h * SEQL + tid] - maxv[h]);
    __syncthreads();
    {
        float sv = 0.0f;
#pragma unroll
        for (int i = 0; i < 8; i++) sv += w_sm[wrp * SEQL + lane + i * 32];
#pragma unroll
        for (int o = 16; o > 0; o >>= 1) sv += __shfl_xor_sync(0xffffffffu, sv, o);
        if (lane == 0) sumv[wrp] = sv;
    }
    __syncthreads();

    // ---- attn @ V (V = src), residual, LN1 --------------------------------
    // thread tid owns dims d = 2*tid, 2*tid+1; head = tid>>5 == warp id.
    const int dd = 2 * tid;
    const int hh = tid >> 5;
    const float* sb = src + b * SEQL * DMODEL + dd;
    const float* wrow = &w_sm[hh * SEQL];
    float acc0 = 0.0f, acc1 = 0.0f;
#pragma unroll 4
    for (int mm = 0; mm < SEQL; mm++) {
        float wa = wrow[mm];
        float2 v = *(const float2*)&sb[mm * DMODEL];
        acc0 += wa * v.x;
        acc1 += wa * v.y;
    }
    const float inv_s = 1.0f / sumv[hh];
    float2 s0 = *(const float2*)&src[row * DMODEL + dd];
    float x0 = s0.x + acc0 * inv_s;
    float x1 = s0.y + acc1 * inv_s;

    redA[tid] = x0 + x1;
    redB[tid] = x0 * x0 + x1 * x1;
    __syncthreads();
    for (int st = 128; st > 0; st >>= 1) {
        if (tid < st) { redA[tid] += redA[tid + st]; redB[tid] += redB[tid + st]; }
        __syncthreads();
    }
    const float mu   = redA[0] * (1.0f / DMODEL);
    const float var  = redB[0] * (1.0f / DMODEL) - mu * mu;
    const float rstd = rsqrtf(var + 1e-5f);
    float2 gm = *(const float2*)&gamma1[dd];
    float2 bt = *(const float2*)&beta1[dd];
    float2 o;
    o.x = (x0 - mu) * rstd * gm.x + bt.x;
    o.y = (x1 - mu) * rstd * gm.y + bt.y;
    *(float2*)&g_x1[row * DMODEL + dd] = o;
}

// ---------------------------------------------------------------------------
// K4: FFN GEMM1  g_hid = leaky_relu(g_x1 @ w1 + b1)
// ---------------------------------------------------------------------------
__global__ __launch_bounds__(256) void k_gemm1(const float* __restrict__ w1,
                                               const float* __restrict__ b1) {
    __shared__ __align__(16) float As[16][64];
    __shared__ __align__(16) float Bs[16][64];
    const int col0 = blockIdx.x * 64;
    const int row0 = blockIdx.y * 64;
    const int tid  = threadIdx.x;
    const int tx = tid & 15, ty = tid >> 4;
    float acc[4][4] = {};
    for (int k0 = 0; k0 < DMODEL; k0 += 16) {
        {
            int r = tid >> 2, kg = tid & 3;
            float4 v = *(const float4*)&g_x1[(row0 + r) * DMODEL + k0 + kg * 4];
            As[kg*4+0][r] = v.x; As[kg*4+1][r] = v.y; As[kg*4+2][r] = v.z; As[kg*4+3][r] = v.w;
        }
        {
            int k = tid >> 4, cg = tid & 15;
            float4 v = *(const float4*)&w1[(k0 + k) * DFF + col0 + cg * 4];
            *(float4*)&Bs[k][cg * 4] = v;
        }
        __syncthreads();
#pragma unroll
        for (int k = 0; k < 16; k++) {
            float a[4], c[4];
            *(float4*)a = *(const float4*)&As[k][ty * 4];
            *(float4*)c = *(const float4*)&Bs[k][tx * 4];
#pragma unroll
            for (int i = 0; i < 4; i++)
#pragma unroll
                for (int j = 0; j < 4; j++) acc[i][j] += a[i] * c[j];
        }
        __syncthreads();
    }
#pragma unroll
    for (int i = 0; i < 4; i++) {
        float4 o;
        float v0 = acc[i][0] + b1[col0 + tx*4 + 0];
        float v1 = acc[i][1] + b1[col0 + tx*4 + 1];
        float v2 = acc[i][2] + b1[col0 + tx*4 + 2];
        float v3 = acc[i][3] + b1[col0 + tx*4 + 3];
        o.x = v0 > 0.0f ? v0 : 0.01f * v0;
        o.y = v1 > 0.0f ? v1 : 0.01f * v1;
        o.z = v2 > 0.0f ? v2 : 0.01f * v2;
        o.w = v3 > 0.0f ? v3 : 0.01f * v3;
        *(float4*)&g_hid[(row0 + ty*4 + i) * DFF + col0 + tx * 4] = o;
    }
}

// ---------------------------------------------------------------------------
// K5: FFN GEMM2 (split-K, deterministic partials)
// ---------------------------------------------------------------------------
__global__ __launch_bounds__(256) void k_gemm2(const float* __restrict__ w2) {
    __shared__ __align__(16) float As[16][64];
    __shared__ __align__(16) float Bs[16][64];
    const int col0 = blockIdx.x * 64;
    const int row0 = blockIdx.y * 64;
    const int kz   = blockIdx.z;
    const int tid  = threadIdx.x;
    const int tx = tid & 15, ty = tid >> 4;
    const int kbeg = kz * (DFF / KSPLIT);
    float acc[4][4] = {};
    for (int kc = 0; kc < DFF / KSPLIT; kc += 16) {
        int k0 = kbeg + kc;
        {
            int r = tid >> 2, kg = tid & 3;
            float4 v = *(const float4*)&g_hid[(row0 + r) * DFF + k0 + kg * 4];
            As[kg*4+0][r] = v.x; As[kg*4+1][r] = v.y; As[kg*4+2][r] = v.z; As[kg*4+3][r] = v.w;
        }
        {
            int k = tid >> 4, cg = tid & 15;
            float4 v = *(const float4*)&w2[(k0 + k) * DMODEL + col0 + cg * 4];
            *(float4*)&Bs[k][cg * 4] = v;
        }
        __syncthreads();
#pragma unroll
        for (int k = 0; k < 16; k++) {
            float a[4], c[4];
            *(float4*)a = *(const float4*)&As[k][ty * 4];
            *(float4*)c = *(const float4*)&Bs[k][tx * 4];
#pragma unroll
            for (int i = 0; i < 4; i++)
#pragma unroll
                for (int j = 0; j < 4; j++) acc[i][j] += a[i] * c[j];
        }
        __syncthreads();
    }
#pragma unroll
    for (int i = 0; i < 4; i++) {
        float4 o = make_float4(acc[i][0], acc[i][1], acc[i][2], acc[i][3]);
        *(float4*)&g_yp[kz * NROWS * DMODEL + (row0 + ty*4 + i) * DMODEL + col0 + tx * 4] = o;
    }
}

// ---------------------------------------------------------------------------
// K6: combine split-K partials + b2 + residual(x) -> LN2 -> out
// ---------------------------------------------------------------------------
__global__ __launch_bounds__(256) void k_ln2(const float* __restrict__ b2,
                                             const float* __restrict__ gamma2,
                                             const float* __restrict__ beta2,
                                             float* __restrict__ out) {
    __shared__ float redA[256], redB[256];
    const int row = blockIdx.x;
    const int tid = threadIdx.x;
    const int d0 = tid, d1 = tid + 256;
    float y0 = g_x1[row * DMODEL + d0] + b2[d0];
    float y1 = g_x1[row * DMODEL + d1] + b2[d1];
#pragma unroll
    for (int kz = 0; kz < KSPLIT; kz++) {
        y0 += g_yp[kz * NROWS * DMODEL + row * DMODEL + d0];
        y1 += g_yp[kz * NROWS * DMODEL + row * DMODEL + d1];
    }
    redA[tid] = y0 + y1;
    redB[tid] = y0 * y0 + y1 * y1;
    __syncthreads();
    for (int st = 128; st > 0; st >>= 1) {
        if (tid < st) { redA[tid] += redA[tid + st]; redB[tid] += redB[tid + st]; }
        __syncthreads();
    }
    const float mu   = redA[0] * (1.0f / DMODEL);
    const float var  = redB[0] * (1.0f / DMODEL) - mu * mu;
    const float rstd = rsqrtf(var + 1e-5f);
    out[row * DMODEL + d0] = (y0 - mu) * rstd * gamma2[d0] + beta2[d0];
    out[row * DMODEL + d1] = (y1 - mu) * rstd * gamma2[d1] + beta2[d1];
}

// ---------------------------------------------------------------------------
extern "C" void kernel_launch(void* const* d_in, const int* in_sizes, int n_in,
                              void* d_out, int out_size) {
    (void)in_sizes; (void)n_in; (void)out_size;
    const float* src      = (const float*)d_in[0];
    const float* rel_diss = (const float*)d_in[1];
    const float* rel_dirs = (const float*)d_in[2];
    const float* rp_w     = (const float*)d_in[3];
    const float* rp_b     = (const float*)d_in[4];
    const float* w1       = (const float*)d_in[5];
    const float* b1       = (const float*)d_in[6];
    const float* w2       = (const float*)d_in[7];
    const float* b2       = (const float*)d_in[8];
    const float* gamma1   = (const float*)d_in[9];
    const float* beta1    = (const float*)d_in[10];
    const float* gamma2   = (const float*)d_in[11];
    const float* beta2    = (const float*)d_in[12];
    float* out = (float*)d_out;

    k_vw   <<<dim3(NF/64, NROWS/64, NHEADS), 256>>>(src, rp_w);
    k_cb   <<<(NROWS*NHEADS + 255)/256, 256>>>(src, rp_b);
    k_base <<<dim3(SEQL/64, SEQL/64, NB*NHEADS), 256>>>(src);
    k_attn <<<NROWS, 256>>>(src, rel_diss, rel_dirs, gamma1, beta1);
    k_gemm1<<<dim3(DFF/64, NROWS/64), 256>>>(w1, b1);
    k_gemm2<<<dim3(DMODEL/64, NROWS/64, KSPLIT), 256>>>(w2);
    k_ln2  <<<NROWS, 256>>>(b2, gamma2, beta2, out);
}

// round 3
// speedup vs baseline: 1.2191x; 1.0526x over previous
#include <cuda_runtime.h>

// ---------------------------------------------------------------------------
// Transformer block with RBF x spherical-harmonic relative-position encoding.
// rp path factorized: vw[b,l,h,f] = sum_dh rp_w[f,h*64+dh]*q[b,l,h,dh], then
// rp_scores = env * sum_r g[r] * (sum_s sph_s * vw[...,s*64+r]) + cb.
// R2->R3: Gaussian window sparsity in k_attn — only 16 of 64 radial centers
// within ~1.0 of d contribute (> 3e-10); r-loop cut 16->4 iterations.
// ---------------------------------------------------------------------------

#define CUTOFF  10.0f
#define NRAD    64
#define NSPH    9
#define NHEADS  8
#define DMODEL  512
#define DHEAD   64
#define SEQL    256
#define NB      2
#define NROWS   (NB*SEQL)      // 512
#define NF      (NRAD*NSPH)    // 576
#define DFF     2048
#define KSPLIT  4

__device__ __align__(16) float g_vw[NROWS*NHEADS*NF];          // [row][h][f]
__device__ __align__(16) float g_cb[NROWS*NHEADS];
__device__ __align__(16) float g_base[NB*NHEADS*SEQL*SEQL];    // [b][h][l][m]
__device__ __align__(16) float g_x1[NROWS*DMODEL];
__device__ __align__(16) float g_hid[NROWS*DFF];
__device__ __align__(16) float g_yp[KSPLIT*NROWS*DMODEL];

// ---------------------------------------------------------------------------
// K1: vw[row, h, f] = sum_dh src[row, h*64+dh] * rp_w[f, h*64+dh]
// ---------------------------------------------------------------------------
__global__ __launch_bounds__(256) void k_vw(const float* __restrict__ src,
                                            const float* __restrict__ rp_w) {
    __shared__ __align__(16) float As[64][64];   // [dh][row]
    __shared__ __align__(16) float Bs[64][64];   // [dh][f]
    const int f0   = blockIdx.x * 64;
    const int row0 = blockIdx.y * 64;
    const int h    = blockIdx.z;
    const int tid  = threadIdx.x;
#pragma unroll
    for (int i = 0; i < 4; i++) {
        int lin = i * 256 + tid;
        int r   = lin >> 4;
        int k4  = lin & 15;
        float4 a = *(const float4*)&src [(row0 + r) * DMODEL + h * DHEAD + k4 * 4];
        As[k4*4+0][r] = a.x; As[k4*4+1][r] = a.y; As[k4*4+2][r] = a.z; As[k4*4+3][r] = a.w;
        float4 b = *(const float4*)&rp_w[(f0   + r) * DMODEL + h * DHEAD + k4 * 4];
        Bs[k4*4+0][r] = b.x; Bs[k4*4+1][r] = b.y; Bs[k4*4+2][r] = b.z; Bs[k4*4+3][r] = b.w;
    }
    __syncthreads();
    const int tx = tid & 15, ty = tid >> 4;
    float acc[4][4] = {};
#pragma unroll
    for (int k = 0; k < 64; k++) {
        float a[4], b[4];
        *(float4*)a = *(const float4*)&As[k][ty * 4];
        *(float4*)b = *(const float4*)&Bs[k][tx * 4];
#pragma unroll
        for (int i = 0; i < 4; i++)
#pragma unroll
            for (int j = 0; j < 4; j++) acc[i][j] += a[i] * b[j];
    }
#pragma unroll
    for (int i = 0; i < 4; i++) {
        float4 o = make_float4(acc[i][0], acc[i][1], acc[i][2], acc[i][3]);
        *(float4*)&g_vw[(row0 + ty*4 + i) * (NHEADS*NF) + h * NF + f0 + tx * 4] = o;
    }
}

// ---------------------------------------------------------------------------
// K1b: cb[row,h] = sum_dh rp_b[h*64+dh]*src[row, h*64+dh]
// ---------------------------------------------------------------------------
__global__ void k_cb(const float* __restrict__ src, const float* __restrict__ rp_b) {
    int i = blockIdx.x * blockDim.x + threadIdx.x;
    if (i >= NROWS * NHEADS) return;
    int row = i >> 3, h = i & 7;
    const float* s  = &src[row * DMODEL + h * DHEAD];
    const float* bb = &rp_b[h * DHEAD];
    float acc = 0.0f;
#pragma unroll
    for (int k = 0; k < DHEAD; k++) acc += s[k] * bb[k];
    g_cb[i] = acc;
}

// ---------------------------------------------------------------------------
// K2: base[b,h,l,m] = (1/8) * sum_dh q[b,l,h,dh]*q[b,m,h,dh]
// ---------------------------------------------------------------------------
__global__ __launch_bounds__(256) void k_base(const float* __restrict__ src) {
    __shared__ __align__(16) float As[64][64];
    __shared__ __align__(16) float Bs[64][64];
    const int m0 = blockIdx.x * 64;
    const int l0 = blockIdx.y * 64;
    const int b  = blockIdx.z >> 3;
    const int h  = blockIdx.z & 7;
    const int tid = threadIdx.x;
    const float* sb = src + b * SEQL * DMODEL;
#pragma unroll
    for (int i = 0; i < 4; i++) {
        int lin = i * 256 + tid;
        int r   = lin >> 4;
        int k4  = lin & 15;
        float4 a = *(const float4*)&sb[(l0 + r) * DMODEL + h * DHEAD + k4 * 4];
        As[k4*4+0][r] = a.x; As[k4*4+1][r] = a.y; As[k4*4+2][r] = a.z; As[k4*4+3][r] = a.w;
        float4 c = *(const float4*)&sb[(m0 + r) * DMODEL + h * DHEAD + k4 * 4];
        Bs[k4*4+0][r] = c.x; Bs[k4*4+1][r] = c.y; Bs[k4*4+2][r] = c.z; Bs[k4*4+3][r] = c.w;
    }
    __syncthreads();
    const int tx = tid & 15, ty = tid >> 4;
    float acc[4][4] = {};
#pragma unroll
    for (int k = 0; k < 64; k++) {
        float a[4], c[4];
        *(float4*)a = *(const float4*)&As[k][ty * 4];
        *(float4*)c = *(const float4*)&Bs[k][tx * 4];
#pragma unroll
        for (int i = 0; i < 4; i++)
#pragma unroll
            for (int j = 0; j < 4; j++) acc[i][j] += a[i] * c[j];
    }
#pragma unroll
    for (int i = 0; i < 4; i++) {
        float4 o = make_float4(acc[i][0]*0.125f, acc[i][1]*0.125f,
                               acc[i][2]*0.125f, acc[i][3]*0.125f);
        *(float4*)&g_base[((b*NHEADS + h)*SEQL + l0 + ty*4 + i) * SEQL + m0 + tx*4] = o;
    }
}

// ---------------------------------------------------------------------------
// K3: fused per-(b,l): rp scores + softmax + attn@V + residual + LN1.
// Radial contraction restricted to a 16-center window around d.
// ---------------------------------------------------------------------------
__global__ __launch_bounds__(256, 3) void k_attn(
    const float* __restrict__ src, const float* __restrict__ rel_diss,
    const float* __restrict__ rel_dirs, const float* __restrict__ gamma1,
    const float* __restrict__ beta1) {
    __shared__ __align__(16) float vw_sm[NHEADS * NF];   // 18 KB
    __shared__ float w_sm[NHEADS * SEQL];                // 8 KB
    __shared__ float cb_sm[NHEADS];
    __shared__ float maxv[NHEADS], sumv[NHEADS];
    __shared__ float redA[256], redB[256];

    const int row = blockIdx.x;        // b*256 + l
    const int b   = row >> 8;
    const int l   = row & 255;
    const int tid = threadIdx.x;

    {   // stage vw for this (b,l) into smem
        const float4* vs = (const float4*)&g_vw[row * (NHEADS * NF)];
        float4* vd = (float4*)vw_sm;
        for (int i = tid; i < (NHEADS * NF) / 4; i += 256) vd[i] = vs[i];
        if (tid < NHEADS) cb_sm[tid] = g_cb[row * NHEADS + tid];
    }
    __syncthreads();

    // ---- per-m edge features + windowed contraction -----------------------
    const int m = tid;
    const float d  = rel_diss[row * SEQL + m];
    const float dx = rel_dirs[(row * SEQL + m) * 3 + 0];
    const float dy = rel_dirs[(row * SEQL + m) * 3 + 1];
    const float dz = rel_dirs[(row * SEQL + m) * 3 + 2];
    const float dc  = fminf(fmaxf(d * (1.0f / CUTOFF), 0.0f), 1.0f);
    const float env = 0.5f * (__cosf(3.14159265358979f * dc) + 1.0f);

    float sp[9];
    sp[0] = 0.28209479177387814f;
    sp[1] = 0.4886025119029199f * dy;
    sp[2] = 0.4886025119029199f * dz;
    sp[3] = 0.4886025119029199f * dx;
    sp[4] = 1.0925484305920792f * dx * dy;
    sp[5] = 1.0925484305920792f * dy * dz;
    sp[6] = 0.31539156525252005f * (3.0f * dz * dz - 1.0f);
    sp[7] = 1.0925484305920792f * dx * dz;
    sp[8] = 0.5462742152960396f * (dx * dx - dy * dy);

    float rp[NHEADS];
#pragma unroll
    for (int h = 0; h < NHEADS; h++) rp[h] = 0.0f;

    const float inv2w2 = 20.48f;                  // 1/(2*(CUTOFF/NRAD)^2)
    const float cstep  = CUTOFF / 63.0f;          // linspace(0,10,64) step

    // 16-center aligned window around d: dropped terms < 3e-10.
    int ic = (int)floorf(d * (63.0f / CUTOFF) + 0.5f);   // nearest center idx
    int r0 = (ic - 6) & ~3;
    r0 = min(max(r0, 0), NRAD - 16);
    const float* vwp = vw_sm + r0;
    const float base_d = d - (float)r0 * cstep;

#pragma unroll
    for (int j = 0; j < 4; j++) {
        float f0 = base_d - (float)(4*j + 0) * cstep;
        float f1 = base_d - (float)(4*j + 1) * cstep;
        float f2 = base_d - (float)(4*j + 2) * cstep;
        float f3 = base_d - (float)(4*j + 3) * cstep;
        float g0 = __expf(-f0 * f0 * inv2w2);
        float g1 = __expf(-f1 * f1 * inv2w2);
        float g2 = __expf(-f2 * f2 * inv2w2);
        float g3 = __expf(-f3 * f3 * inv2w2);
#pragma unroll
        for (int h = 0; h < NHEADS; h++) {
            float ux = 0.0f, uy = 0.0f, uz = 0.0f, uw = 0.0f;
#pragma unroll
            for (int s = 0; s < NSPH; s++) {
                float4 v = *(const float4*)&vwp[h * NF + s * NRAD + 4 * j];
                ux += sp[s] * v.x; uy += sp[s] * v.y;
                uz += sp[s] * v.z; uw += sp[s] * v.w;
            }
            rp[h] += g0 * ux + g1 * uy + g2 * uz + g3 * uw;
        }
    }

#pragma unroll
    for (int h = 0; h < NHEADS; h++) {
        w_sm[h * SEQL + m] = g_base[((b * NHEADS + h) * SEQL + l) * SEQL + m]
                           + env * rp[h] + cb_sm[h];
    }
    __syncthreads();

    // ---- softmax over m (warp w reduces head h=w) -------------------------
    const int wrp = tid >> 5, lane = tid & 31;
    {
        float mv = -1e30f;
#pragma unroll
        for (int i = 0; i < 8; i++) mv = fmaxf(mv, w_sm[wrp * SEQL + lane + i * 32]);
#pragma unroll
        for (int o = 16; o > 0; o >>= 1) mv = fmaxf(mv, __shfl_xor_sync(0xffffffffu, mv, o));
        if (lane == 0) maxv[wrp] = mv;
    }
    __syncthreads();
#pragma unroll
    for (int h = 0; h < NHEADS; h++)
        w_sm[h * SEQL + tid] = __expf(w_sm[h * SEQL + tid] - maxv[h]);
    __syncthreads();
    {
        float sv = 0.0f;
#pragma unroll
        for (int i = 0; i < 8; i++) sv += w_sm[wrp * SEQL + lane + i * 32];
#pragma unroll
        for (int o = 16; o > 0; o >>= 1) sv += __shfl_xor_sync(0xffffffffu, sv, o);
        if (lane == 0) sumv[wrp] = sv;
    }
    __syncthreads();

    // ---- attn @ V (V = src), residual, LN1 --------------------------------
    const int dd = 2 * tid;
    const int hh = tid >> 5;
    const float* sb = src + b * SEQL * DMODEL + dd;
    const float* wrow = &w_sm[hh * SEQL];
    float acc0 = 0.0f, acc1 = 0.0f;
#pragma unroll 4
    for (int mm = 0; mm < SEQL; mm++) {
        float wa = wrow[mm];
        float2 v = *(const float2*)&sb[mm * DMODEL];
        acc0 += wa * v.x;
        acc1 += wa * v.y;
    }
    const float inv_s = 1.0f / sumv[hh];
    float2 s0 = *(const float2*)&src[row * DMODEL + dd];
    float x0 = s0.x + acc0 * inv_s;
    float x1 = s0.y + acc1 * inv_s;

    redA[tid] = x0 + x1;
    redB[tid] = x0 * x0 + x1 * x1;
    __syncthreads();
    for (int st = 128; st > 0; st >>= 1) {
        if (tid < st) { redA[tid] += redA[tid + st]; redB[tid] += redB[tid + st]; }
        __syncthreads();
    }
    const float mu   = redA[0] * (1.0f / DMODEL);
    const float var  = redB[0] * (1.0f / DMODEL) - mu * mu;
    const float rstd = rsqrtf(var + 1e-5f);
    float2 gm = *(const float2*)&gamma1[dd];
    float2 bt = *(const float2*)&beta1[dd];
    float2 o;
    o.x = (x0 - mu) * rstd * gm.x + bt.x;
    o.y = (x1 - mu) * rstd * gm.y + bt.y;
    *(float2*)&g_x1[row * DMODEL + dd] = o;
}

// ---------------------------------------------------------------------------
// K4: FFN GEMM1  g_hid = leaky_relu(g_x1 @ w1 + b1)
// ---------------------------------------------------------------------------
__global__ __launch_bounds__(256) void k_gemm1(const float* __restrict__ w1,
                                               const float* __restrict__ b1) {
    __shared__ __align__(16) float As[16][64];
    __shared__ __align__(16) float Bs[16][64];
    const int col0 = blockIdx.x * 64;
    const int row0 = blockIdx.y * 64;
    const int tid  = threadIdx.x;
    const int tx = tid & 15, ty = tid >> 4;
    float acc[4][4] = {};
    for (int k0 = 0; k0 < DMODEL; k0 += 16) {
        {
            int r = tid >> 2, kg = tid & 3;
            float4 v = *(const float4*)&g_x1[(row0 + r) * DMODEL + k0 + kg * 4];
            As[kg*4+0][r] = v.x; As[kg*4+1][r] = v.y; As[kg*4+2][r] = v.z; As[kg*4+3][r] = v.w;
        }
        {
            int k = tid >> 4, cg = tid & 15;
            float4 v = *(const float4*)&w1[(k0 + k) * DFF + col0 + cg * 4];
            *(float4*)&Bs[k][cg * 4] = v;
        }
        __syncthreads();
#pragma unroll
        for (int k = 0; k < 16; k++) {
            float a[4], c[4];
            *(float4*)a = *(const float4*)&As[k][ty * 4];
            *(float4*)c = *(const float4*)&Bs[k][tx * 4];
#pragma unroll
            for (int i = 0; i < 4; i++)
#pragma unroll
                for (int j = 0; j < 4; j++) acc[i][j] += a[i] * c[j];
        }
        __syncthreads();
    }
#pragma unroll
    for (int i = 0; i < 4; i++) {
        float4 o;
        float v0 = acc[i][0] + b1[col0 + tx*4 + 0];
        float v1 = acc[i][1] + b1[col0 + tx*4 + 1];
        float v2 = acc[i][2] + b1[col0 + tx*4 + 2];
        float v3 = acc[i][3] + b1[col0 + tx*4 + 3];
        o.x = v0 > 0.0f ? v0 : 0.01f * v0;
        o.y = v1 > 0.0f ? v1 : 0.01f * v1;
        o.z = v2 > 0.0f ? v2 : 0.01f * v2;
        o.w = v3 > 0.0f ? v3 : 0.01f * v3;
        *(float4*)&g_hid[(row0 + ty*4 + i) * DFF + col0 + tx * 4] = o;
    }
}

// ---------------------------------------------------------------------------
// K5: FFN GEMM2 (split-K, deterministic partials)
// ---------------------------------------------------------------------------
__global__ __launch_bounds__(256) void k_gemm2(const float* __restrict__ w2) {
    __shared__ __align__(16) float As[16][64];
    __shared__ __align__(16) float Bs[16][64];
    const int col0 = blockIdx.x * 64;
    const int row0 = blockIdx.y * 64;
    const int kz   = blockIdx.z;
    const int tid  = threadIdx.x;
    const int tx = tid & 15, ty = tid >> 4;
    const int kbeg = kz * (DFF / KSPLIT);
    float acc[4][4] = {};
    for (int kc = 0; kc < DFF / KSPLIT; kc += 16) {
        int k0 = kbeg + kc;
        {
            int r = tid >> 2, kg = tid & 3;
            float4 v = *(const float4*)&g_hid[(row0 + r) * DFF + k0 + kg * 4];
            As[kg*4+0][r] = v.x; As[kg*4+1][r] = v.y; As[kg*4+2][r] = v.z; As[kg*4+3][r] = v.w;
        }
        {
            int k = tid >> 4, cg = tid & 15;
            float4 v = *(const float4*)&w2[(k0 + k) * DMODEL + col0 + cg * 4];
            *(float4*)&Bs[k][cg * 4] = v;
        }
        __syncthreads();
#pragma unroll
        for (int k = 0; k < 16; k++) {
            float a[4], c[4];
            *(float4*)a = *(const float4*)&As[k][ty * 4];
            *(float4*)c = *(const float4*)&Bs[k][tx * 4];
#pragma unroll
            for (int i = 0; i < 4; i++)
#pragma unroll
                for (int j = 0; j < 4; j++) acc[i][j] += a[i] * c[j];
        }
        __syncthreads();
    }
#pragma unroll
    for (int i = 0; i < 4; i++) {
        float4 o = make_float4(acc[i][0], acc[i][1], acc[i][2], acc[i][3]);
        *(float4*)&g_yp[kz * NROWS * DMODEL + (row0 + ty*4 + i) * DMODEL + col0 + tx * 4] = o;
    }
}

// ---------------------------------------------------------------------------
// K6: combine split-K partials + b2 + residual(x) -> LN2 -> out
// ---------------------------------------------------------------------------
__global__ __launch_bounds__(256) void k_ln2(const float* __restrict__ b2,
                                             const float* __restrict__ gamma2,
                                             const float* __restrict__ beta2,
                                             float* __restrict__ out) {
    __shared__ float redA[256], redB[256];
    const int row = blockIdx.x;
    const int tid = threadIdx.x;
    const int d0 = tid, d1 = tid + 256;
    float y0 = g_x1[row * DMODEL + d0] + b2[d0];
    float y1 = g_x1[row * DMODEL + d1] + b2[d1];
#pragma unroll
    for (int kz = 0; kz < KSPLIT; kz++) {
        y0 += g_yp[kz * NROWS * DMODEL + row * DMODEL + d0];
        y1 += g_yp[kz * NROWS * DMODEL + row * DMODEL + d1];
    }
    redA[tid] = y0 + y1;
    redB[tid] = y0 * y0 + y1 * y1;
    __syncthreads();
    for (int st = 128; st > 0; st >>= 1) {
        if (tid < st) { redA[tid] += redA[tid + st]; redB[tid] += redB[tid + st]; }
        __syncthreads();
    }
    const float mu   = redA[0] * (1.0f / DMODEL);
    const float var  = redB[0] * (1.0f / DMODEL) - mu * mu;
    const float rstd = rsqrtf(var + 1e-5f);
    out[row * DMODEL + d0] = (y0 - mu) * rstd * gamma2[d0] + beta2[d0];
    out[row * DMODEL + d1] = (y1 - mu) * rstd * gamma2[d1] + beta2[d1];
}

// ---------------------------------------------------------------------------
extern "C" void kernel_launch(void* const* d_in, const int* in_sizes, int n_in,
                              void* d_out, int out_size) {
    (void)in_sizes; (void)n_in; (void)out_size;
    const float* src      = (const float*)d_in[0];
    const float* rel_diss = (const float*)d_in[1];
    const float* rel_dirs = (const float*)d_in[2];
    const float* rp_w     = (const float*)d_in[3];
    const float* rp_b     = (const float*)d_in[4];
    const float* w1       = (const float*)d_in[5];
    const float* b1       = (const float*)d_in[6];
    const float* w2       = (const float*)d_in[7];
    const float* b2       = (const float*)d_in[8];
    const float* gamma1   = (const float*)d_in[9];
    const float* beta1    = (const float*)d_in[10];
    const float* gamma2   = (const float*)d_in[11];
    const float* beta2    = (const float*)d_in[12];
    float* out = (float*)d_out;

    k_vw   <<<dim3(NF/64, NROWS/64, NHEADS), 256>>>(src, rp_w);
    k_cb   <<<(NROWS*NHEADS + 255)/256, 256>>>(src, rp_b);
    k_base <<<dim3(SEQL/64, SEQL/64, NB*NHEADS), 256>>>(src);
    k_attn <<<NROWS, 256>>>(src, rel_diss, rel_dirs, gamma1, beta1);
    k_gemm1<<<dim3(DFF/64, NROWS/64), 256>>>(w1, b1);
    k_gemm2<<<dim3(DMODEL/64, NROWS/64, KSPLIT), 256>>>(w2);
    k_ln2  <<<NROWS, 256>>>(b2, gamma2, beta2, out);
}

// round 4
// speedup vs baseline: 1.3424x; 1.1011x over previous
#include <cuda_runtime.h>

// ---------------------------------------------------------------------------
// Transformer block with RBF x spherical-harmonic relative-position encoding.
// R3->R4: k_attn split into k_scores (warp-per-m, conflict-free padded vw,
// normalized weights written to g_base) + k_av (tiled smem GEMM) + k_ln1.
// ---------------------------------------------------------------------------

#define CUTOFF  10.0f
#define NRAD    64
#define NSPH    9
#define NHEADS  8
#define DMODEL  512
#define DHEAD   64
#define SEQL    256
#define NB      2
#define NROWS   (NB*SEQL)      // 512
#define NF      (NRAD*NSPH)    // 576
#define DFF     2048
#define KSPLIT  4

// padded vw layout: h-stride 604 words (604 % 32 == 28 -> bank-staggered)
#define VW_H    604
#define VW_ROW  (NHEADS*VW_H)  // 4832 words per row
#define WS      260            // w_sm head stride (260 % 32 == 4)

__device__ __align__(16) float g_vw[NROWS*VW_ROW];             // padded [row][h][f]
__device__ __align__(16) float g_cb[NROWS*NHEADS];
__device__ __align__(16) float g_base[NB*NHEADS*SEQL*SEQL];    // logits -> weights
__device__ __align__(16) float g_attn[NROWS*DMODEL];
__device__ __align__(16) float g_x1[NROWS*DMODEL];
__device__ __align__(16) float g_hid[NROWS*DFF];
__device__ __align__(16) float g_yp[KSPLIT*NROWS*DMODEL];

// ---------------------------------------------------------------------------
// K1: vw[row, h, f] = sum_dh src[row, h*64+dh] * rp_w[f, h*64+dh]  (padded out)
// ---------------------------------------------------------------------------
__global__ __launch_bounds__(256) void k_vw(const float* __restrict__ src,
                                            const float* __restrict__ rp_w) {
    __shared__ __align__(16) float As[64][64];   // [dh][row]
    __shared__ __align__(16) float Bs[64][64];   // [dh][f]
    const int f0   = blockIdx.x * 64;
    const int row0 = blockIdx.y * 64;
    const int h    = blockIdx.z;
    const int tid  = threadIdx.x;
#pragma unroll
    for (int i = 0; i < 4; i++) {
        int lin = i * 256 + tid;
        int r   = lin >> 4;
        int k4  = lin & 15;
        float4 a = *(const float4*)&src [(row0 + r) * DMODEL + h * DHEAD + k4 * 4];
        As[k4*4+0][r] = a.x; As[k4*4+1][r] = a.y; As[k4*4+2][r] = a.z; As[k4*4+3][r] = a.w;
        float4 b = *(const float4*)&rp_w[(f0   + r) * DMODEL + h * DHEAD + k4 * 4];
        Bs[k4*4+0][r] = b.x; Bs[k4*4+1][r] = b.y; Bs[k4*4+2][r] = b.z; Bs[k4*4+3][r] = b.w;
    }
    __syncthreads();
    const int tx = tid & 15, ty = tid >> 4;
    float acc[4][4] = {};
#pragma unroll
    for (int k = 0; k < 64; k++) {
        float a[4], b[4];
        *(float4*)a = *(const float4*)&As[k][ty * 4];
        *(float4*)b = *(const float4*)&Bs[k][tx * 4];
#pragma unroll
        for (int i = 0; i < 4; i++)
#pragma unroll
            for (int j = 0; j < 4; j++) acc[i][j] += a[i] * b[j];
    }
#pragma unroll
    for (int i = 0; i < 4; i++) {
        float4 o = make_float4(acc[i][0], acc[i][1], acc[i][2], acc[i][3]);
        *(float4*)&g_vw[(row0 + ty*4 + i) * VW_ROW + h * VW_H + f0 + tx * 4] = o;
    }
}

// ---------------------------------------------------------------------------
// K1b: cb[row,h] = sum_dh rp_b[h*64+dh]*src[row, h*64+dh]
// ---------------------------------------------------------------------------
__global__ void k_cb(const float* __restrict__ src, const float* __restrict__ rp_b) {
    int i = blockIdx.x * blockDim.x + threadIdx.x;
    if (i >= NROWS * NHEADS) return;
    int row = i >> 3, h = i & 7;
    const float* s  = &src[row * DMODEL + h * DHEAD];
    const float* bb = &rp_b[h * DHEAD];
    float acc = 0.0f;
#pragma unroll
    for (int k = 0; k < DHEAD; k++) acc += s[k] * bb[k];
    g_cb[i] = acc;
}

// ---------------------------------------------------------------------------
// K2: base[b,h,l,m] = (1/8) * sum_dh q[b,l,h,dh]*q[b,m,h,dh]
// ---------------------------------------------------------------------------
__global__ __launch_bounds__(256) void k_base(const float* __restrict__ src) {
    __shared__ __align__(16) float As[64][64];
    __shared__ __align__(16) float Bs[64][64];
    const int m0 = blockIdx.x * 64;
    const int l0 = blockIdx.y * 64;
    const int b  = blockIdx.z >> 3;
    const int h  = blockIdx.z & 7;
    const int tid = threadIdx.x;
    const float* sb = src + b * SEQL * DMODEL;
#pragma unroll
    for (int i = 0; i < 4; i++) {
        int lin = i * 256 + tid;
        int r   = lin >> 4;
        int k4  = lin & 15;
        float4 a = *(const float4*)&sb[(l0 + r) * DMODEL + h * DHEAD + k4 * 4];
        As[k4*4+0][r] = a.x; As[k4*4+1][r] = a.y; As[k4*4+2][r] = a.z; As[k4*4+3][r] = a.w;
        float4 c = *(const float4*)&sb[(m0 + r) * DMODEL + h * DHEAD + k4 * 4];
        Bs[k4*4+0][r] = c.x; Bs[k4*4+1][r] = c.y; Bs[k4*4+2][r] = c.z; Bs[k4*4+3][r] = c.w;
    }
    __syncthreads();
    const int tx = tid & 15, ty = tid >> 4;
    float acc[4][4] = {};
#pragma unroll
    for (int k = 0; k < 64; k++) {
        float a[4], c[4];
        *(float4*)a = *(const float4*)&As[k][ty * 4];
        *(float4*)c = *(const float4*)&Bs[k][tx * 4];
#pragma unroll
        for (int i = 0; i < 4; i++)
#pragma unroll
            for (int j = 0; j < 4; j++) acc[i][j] += a[i] * c[j];
    }
#pragma unroll
    for (int i = 0; i < 4; i++) {
        float4 o = make_float4(acc[i][0]*0.125f, acc[i][1]*0.125f,
                               acc[i][2]*0.125f, acc[i][3]*0.125f);
        *(float4*)&g_base[((b*NHEADS + h)*SEQL + l0 + ty*4 + i) * SEQL + m0 + tx*4] = o;
    }
}

// ---------------------------------------------------------------------------
// K3: scores + softmax. One warp per key m; lanes = (h, r-quad).
// Writes NORMALIZED attention weights back into g_base.
// ---------------------------------------------------------------------------
__global__ __launch_bounds__(256, 3) void k_scores(
    const float* __restrict__ rel_diss, const float* __restrict__ rel_dirs) {
    __shared__ __align__(16) float vw_sm[VW_ROW];    // 19328 B
    __shared__ float w_sm[NHEADS * WS];              // 8320 B
    __shared__ float cb_sm[NHEADS];
    __shared__ float maxv[NHEADS], sumv[NHEADS];

    const int row = blockIdx.x;        // b*256 + l
    const int b   = row >> 8;
    const int l   = row & 255;
    const int tid = threadIdx.x;

    {   // stage padded vw row
        const float4* vs = (const float4*)&g_vw[row * VW_ROW];
        float4* vd = (float4*)vw_sm;
        for (int i = tid; i < VW_ROW / 4; i += 256) vd[i] = vs[i];
    }
    // stage base logits (coalesced) into w_sm
#pragma unroll
    for (int h = 0; h < NHEADS; h++)
        w_sm[h * WS + tid] = g_base[((b * NHEADS + h) * SEQL + l) * SEQL + tid];
    if (tid < NHEADS) cb_sm[tid] = g_cb[row * NHEADS + tid];
    __syncthreads();

    const int wrp = tid >> 5, lane = tid & 31;
    const int hh = lane & 7, rq = lane >> 3;
    const float inv2w2 = 20.48f;
    const float cstep  = CUTOFF / 63.0f;

    for (int i = 0; i < 32; i++) {
        const int m = i * 8 + wrp;
        const float d  = rel_diss[row * SEQL + m];
        const float dx = rel_dirs[(row * SEQL + m) * 3 + 0];
        const float dy = rel_dirs[(row * SEQL + m) * 3 + 1];
        const float dz = rel_dirs[(row * SEQL + m) * 3 + 2];
        const float dc  = fminf(fmaxf(d * (1.0f / CUTOFF), 0.0f), 1.0f);
        const float env = 0.5f * (__cosf(3.14159265358979f * dc) + 1.0f);

        float sp[9];
        sp[0] = 0.28209479177387814f;
        sp[1] = 0.4886025119029199f * dy;
        sp[2] = 0.4886025119029199f * dz;
        sp[3] = 0.4886025119029199f * dx;
        sp[4] = 1.0925484305920792f * dx * dy;
        sp[5] = 1.0925484305920792f * dy * dz;
        sp[6] = 0.31539156525252005f * (3.0f * dz * dz - 1.0f);
        sp[7] = 1.0925484305920792f * dx * dz;
        sp[8] = 0.5462742152960396f * (dx * dx - dy * dy);

        int ic = (int)floorf(d * (63.0f / CUTOFF) + 0.5f);
        int r0 = (ic - 6) & ~3;
        r0 = min(max(r0, 0), NRAD - 16);
        const float base_d = d - (float)r0 * cstep;

        // lane's 4 radial centers: r0 + rq*4 .. +3
        float ux = 0.0f, uy = 0.0f, uz = 0.0f, uw = 0.0f;
        const float* vp = &vw_sm[hh * VW_H + r0 + rq * 4];
#pragma unroll
        for (int s = 0; s < NSPH; s++) {
            float4 v = *(const float4*)&vp[s * NRAD];
            ux += sp[s] * v.x; uy += sp[s] * v.y;
            uz += sp[s] * v.z; uw += sp[s] * v.w;
        }
        float f0 = base_d - (float)(rq * 4 + 0) * cstep;
        float f1 = base_d - (float)(rq * 4 + 1) * cstep;
        float f2 = base_d - (float)(rq * 4 + 2) * cstep;
        float f3 = base_d - (float)(rq * 4 + 3) * cstep;
        float part = __expf(-f0 * f0 * inv2w2) * ux
                   + __expf(-f1 * f1 * inv2w2) * uy
                   + __expf(-f2 * f2 * inv2w2) * uz
                   + __expf(-f3 * f3 * inv2w2) * uw;
        part += __shfl_xor_sync(0xffffffffu, part, 8);
        part += __shfl_xor_sync(0xffffffffu, part, 16);
        if (rq == 0)
            w_sm[hh * WS + m] += env * part + cb_sm[hh];
    }
    __syncthreads();

    // softmax: warp wrp reduces head h=wrp
    {
        float mv = -1e30f;
#pragma unroll
        for (int i = 0; i < 8; i++) mv = fmaxf(mv, w_sm[wrp * WS + lane + i * 32]);
#pragma unroll
        for (int o = 16; o > 0; o >>= 1) mv = fmaxf(mv, __shfl_xor_sync(0xffffffffu, mv, o));
        if (lane == 0) maxv[wrp] = mv;
    }
    __syncthreads();
#pragma unroll
    for (int h = 0; h < NHEADS; h++)
        w_sm[h * WS + tid] = __expf(w_sm[h * WS + tid] - maxv[h]);
    __syncthreads();
    {
        float sv = 0.0f;
#pragma unroll
        for (int i = 0; i < 8; i++) sv += w_sm[wrp * WS + lane + i * 32];
#pragma unroll
        for (int o = 16; o > 0; o >>= 1) sv += __shfl_xor_sync(0xffffffffu, sv, o);
        if (lane == 0) sumv[wrp] = sv;
    }
    __syncthreads();
    // write normalized weights back (coalesced)
#pragma unroll
    for (int h = 0; h < NHEADS; h++) {
        float inv_s = 1.0f / sumv[h];
        g_base[((b * NHEADS + h) * SEQL + l) * SEQL + tid] = w_sm[h * WS + tid] * inv_s;
    }
}

// ---------------------------------------------------------------------------
// K3b: attn output = W @ V as tiled smem GEMM. grid (h, l-tile32, b).
// ---------------------------------------------------------------------------
__global__ __launch_bounds__(256) void k_av(const float* __restrict__ src) {
    __shared__ float Ws[32][33];       // [l][m]
    __shared__ float Vs[32][68];       // [m][dh]
    const int h  = blockIdx.x;
    const int l0 = blockIdx.y * 32;
    const int b  = blockIdx.z;
    const int tid = threadIdx.x;
    const int tx = tid & 15, ty = tid >> 4;        // ty 0..15
    const float* W = g_base + ((b * NHEADS + h) * SEQL) * SEQL;   // [l][m]
    const float* V = src + b * SEQL * DMODEL + h * DHEAD;         // [m][512]

    float acc[2][4] = {};
    for (int mc = 0; mc < 8; mc++) {
        const int m0 = mc * 32;
        {
            int r = tid >> 3, c = tid & 7;
            float4 wv = *(const float4*)&W[(l0 + r) * SEQL + m0 + c * 4];
            Ws[r][c*4+0] = wv.x; Ws[r][c*4+1] = wv.y;
            Ws[r][c*4+2] = wv.z; Ws[r][c*4+3] = wv.w;
            float4 v0 = *(const float4*)&V[(m0 + r) * DMODEL + c * 8];
            float4 v1 = *(const float4*)&V[(m0 + r) * DMODEL + c * 8 + 4];
            Vs[r][c*8+0] = v0.x; Vs[r][c*8+1] = v0.y;
            Vs[r][c*8+2] = v0.z; Vs[r][c*8+3] = v0.w;
            Vs[r][c*8+4] = v1.x; Vs[r][c*8+5] = v1.y;
            Vs[r][c*8+6] = v1.z; Vs[r][c*8+7] = v1.w;
        }
        __syncthreads();
#pragma unroll
        for (int k = 0; k < 32; k++) {
            float a0 = Ws[ty][k];
            float a1 = Ws[ty + 16][k];
            float4 bv = *(const float4*)&Vs[k][tx * 4];
            acc[0][0] += a0 * bv.x; acc[0][1] += a0 * bv.y;
            acc[0][2] += a0 * bv.z; acc[0][3] += a0 * bv.w;
            acc[1][0] += a1 * bv.x; acc[1][1] += a1 * bv.y;
            acc[1][2] += a1 * bv.z; acc[1][3] += a1 * bv.w;
        }
        __syncthreads();
    }
#pragma unroll
    for (int i = 0; i < 2; i++) {
        float4 o = make_float4(acc[i][0], acc[i][1], acc[i][2], acc[i][3]);
        *(float4*)&g_attn[(b * SEQL + l0 + ty + i * 16) * DMODEL + h * DHEAD + tx * 4] = o;
    }
}

// ---------------------------------------------------------------------------
// K3c: x = LN1(src + attn)
// ---------------------------------------------------------------------------
__global__ __launch_bounds__(256) void k_ln1(const float* __restrict__ src,
                                             const float* __restrict__ gamma1,
                                             const float* __restrict__ beta1) {
    __shared__ float redA[256], redB[256];
    const int row = blockIdx.x;
    const int tid = threadIdx.x;
    const int d0 = tid, d1 = tid + 256;
    float x0 = src[row * DMODEL + d0] + g_attn[row * DMODEL + d0];
    float x1 = src[row * DMODEL + d1] + g_attn[row * DMODEL + d1];
    redA[tid] = x0 + x1;
    redB[tid] = x0 * x0 + x1 * x1;
    __syncthreads();
    for (int st = 128; st > 0; st >>= 1) {
        if (tid < st) { redA[tid] += redA[tid + st]; redB[tid] += redB[tid + st]; }
        __syncthreads();
    }
    const float mu   = redA[0] * (1.0f / DMODEL);
    const float var  = redB[0] * (1.0f / DMODEL) - mu * mu;
    const float rstd = rsqrtf(var + 1e-5f);
    g_x1[row * DMODEL + d0] = (x0 - mu) * rstd * gamma1[d0] + beta1[d0];
    g_x1[row * DMODEL + d1] = (x1 - mu) * rstd * gamma1[d1] + beta1[d1];
}

// ---------------------------------------------------------------------------
// K4: FFN GEMM1  g_hid = leaky_relu(g_x1 @ w1 + b1)
// ---------------------------------------------------------------------------
__global__ __launch_bounds__(256) void k_gemm1(const float* __restrict__ w1,
                                               const float* __restrict__ b1) {
    __shared__ __align__(16) float As[16][64];
    __shared__ __align__(16) float Bs[16][64];
    const int col0 = blockIdx.x * 64;
    const int row0 = blockIdx.y * 64;
    const int tid  = threadIdx.x;
    const int tx = tid & 15, ty = tid >> 4;
    float acc[4][4] = {};
    for (int k0 = 0; k0 < DMODEL; k0 += 16) {
        {
            int r = tid >> 2, kg = tid & 3;
            float4 v = *(const float4*)&g_x1[(row0 + r) * DMODEL + k0 + kg * 4];
            As[kg*4+0][r] = v.x; As[kg*4+1][r] = v.y; As[kg*4+2][r] = v.z; As[kg*4+3][r] = v.w;
        }
        {
            int k = tid >> 4, cg = tid & 15;
            float4 v = *(const float4*)&w1[(k0 + k) * DFF + col0 + cg * 4];
            *(float4*)&Bs[k][cg * 4] = v;
        }
        __syncthreads();
#pragma unroll
        for (int k = 0; k < 16; k++) {
            float a[4], c[4];
            *(float4*)a = *(const float4*)&As[k][ty * 4];
            *(float4*)c = *(const float4*)&Bs[k][tx * 4];
#pragma unroll
            for (int i = 0; i < 4; i++)
#pragma unroll
                for (int j = 0; j < 4; j++) acc[i][j] += a[i] * c[j];
        }
        __syncthreads();
    }
#pragma unroll
    for (int i = 0; i < 4; i++) {
        float4 o;
        float v0 = acc[i][0] + b1[col0 + tx*4 + 0];
        float v1 = acc[i][1] + b1[col0 + tx*4 + 1];
        float v2 = acc[i][2] + b1[col0 + tx*4 + 2];
        float v3 = acc[i][3] + b1[col0 + tx*4 + 3];
        o.x = v0 > 0.0f ? v0 : 0.01f * v0;
        o.y = v1 > 0.0f ? v1 : 0.01f * v1;
        o.z = v2 > 0.0f ? v2 : 0.01f * v2;
        o.w = v3 > 0.0f ? v3 : 0.01f * v3;
        *(float4*)&g_hid[(row0 + ty*4 + i) * DFF + col0 + tx * 4] = o;
    }
}

// ---------------------------------------------------------------------------
// K5: FFN GEMM2 (split-K, deterministic partials)
// ---------------------------------------------------------------------------
__global__ __launch_bounds__(256) void k_gemm2(const float* __restrict__ w2) {
    __shared__ __align__(16) float As[16][64];
    __shared__ __align__(16) float Bs[16][64];
    const int col0 = blockIdx.x * 64;
    const int row0 = blockIdx.y * 64;
    const int kz   = blockIdx.z;
    const int tid  = threadIdx.x;
    const int tx = tid & 15, ty = tid >> 4;
    const int kbeg = kz * (DFF / KSPLIT);
    float acc[4][4] = {};
    for (int kc = 0; kc < DFF / KSPLIT; kc += 16) {
        int k0 = kbeg + kc;
        {
            int r = tid >> 2, kg = tid & 3;
            float4 v = *(const float4*)&g_hid[(row0 + r) * DFF + k0 + kg * 4];
            As[kg*4+0][r] = v.x; As[kg*4+1][r] = v.y; As[kg*4+2][r] = v.z; As[kg*4+3][r] = v.w;
        }
        {
            int k = tid >> 4, cg = tid & 15;
            float4 v = *(const float4*)&w2[(k0 + k) * DMODEL + col0 + cg * 4];
            *(float4*)&Bs[k][cg * 4] = v;
        }
        __syncthreads();
#pragma unroll
        for (int k = 0; k < 16; k++) {
            float a[4], c[4];
            *(float4*)a = *(const float4*)&As[k][ty * 4];
            *(float4*)c = *(const float4*)&Bs[k][tx * 4];
#pragma unroll
            for (int i = 0; i < 4; i++)
#pragma unroll
                for (int j = 0; j < 4; j++) acc[i][j] += a[i] * c[j];
        }
        __syncthreads();
    }
#pragma unroll
    for (int i = 0; i < 4; i++) {
        float4 o = make_float4(acc[i][0], acc[i][1], acc[i][2], acc[i][3]);
        *(float4*)&g_yp[kz * NROWS * DMODEL + (row0 + ty*4 + i) * DMODEL + col0 + tx * 4] = o;
    }
}

// ---------------------------------------------------------------------------
// K6: combine split-K partials + b2 + residual(x) -> LN2 -> out
// ---------------------------------------------------------------------------
__global__ __launch_bounds__(256) void k_ln2(const float* __restrict__ b2,
                                             const float* __restrict__ gamma2,
                                             const float* __restrict__ beta2,
                                             float* __restrict__ out) {
    __shared__ float redA[256], redB[256];
    const int row = blockIdx.x;
    const int tid = threadIdx.x;
    const int d0 = tid, d1 = tid + 256;
    float y0 = g_x1[row * DMODEL + d0] + b2[d0];
    float y1 = g_x1[row * DMODEL + d1] + b2[d1];
#pragma unroll
    for (int kz = 0; kz < KSPLIT; kz++) {
        y0 += g_yp[kz * NROWS * DMODEL + row * DMODEL + d0];
        y1 += g_yp[kz * NROWS * DMODEL + row * DMODEL + d1];
    }
    redA[tid] = y0 + y1;
    redB[tid] = y0 * y0 + y1 * y1;
    __syncthreads();
    for (int st = 128; st > 0; st >>= 1) {
        if (tid < st) { redA[tid] += redA[tid + st]; redB[tid] += redB[tid + st]; }
        __syncthreads();
    }
    const float mu   = redA[0] * (1.0f / DMODEL);
    const float var  = redB[0] * (1.0f / DMODEL) - mu * mu;
    const float rstd = rsqrtf(var + 1e-5f);
    out[row * DMODEL + d0] = (y0 - mu) * rstd * gamma2[d0] + beta2[d0];
    out[row * DMODEL + d1] = (y1 - mu) * rstd * gamma2[d1] + beta2[d1];
}

// ---------------------------------------------------------------------------
extern "C" void kernel_launch(void* const* d_in, const int* in_sizes, int n_in,
                              void* d_out, int out_size) {
    (void)in_sizes; (void)n_in; (void)out_size;
    const float* src      = (const float*)d_in[0];
    const float* rel_diss = (const float*)d_in[1];
    const float* rel_dirs = (const float*)d_in[2];
    const float* rp_w     = (const float*)d_in[3];
    const float* rp_b     = (const float*)d_in[4];
    const float* w1       = (const float*)d_in[5];
    const float* b1       = (const float*)d_in[6];
    const float* w2       = (const float*)d_in[7];
    const float* b2       = (const float*)d_in[8];
    const float* gamma1   = (const float*)d_in[9];
    const float* beta1    = (const float*)d_in[10];
    const float* gamma2   = (const float*)d_in[11];
    const float* beta2    = (const float*)d_in[12];
    float* out = (float*)d_out;

    k_vw    <<<dim3(NF/64, NROWS/64, NHEADS), 256>>>(src, rp_w);
    k_cb    <<<(NROWS*NHEADS + 255)/256, 256>>>(src, rp_b);
    k_base  <<<dim3(SEQL/64, SEQL/64, NB*NHEADS), 256>>>(src);
    k_scores<<<NROWS, 256>>>(rel_diss, rel_dirs);
    k_av    <<<dim3(NHEADS, SEQL/32, NB), 256>>>(src);
    k_ln1   <<<NROWS, 256>>>(src, gamma1, beta1);
    k_gemm1 <<<dim3(DFF/64, NROWS/64), 256>>>(w1, b1);
    k_gemm2 <<<dim3(DMODEL/64, NROWS/64, KSPLIT), 256>>>(w2);
    k_ln2   <<<NROWS, 256>>>(b2, gamma2, beta2, out);
}

// round 5
// speedup vs baseline: 1.4444x; 1.0760x over previous
#include <cuda_runtime.h>

// ---------------------------------------------------------------------------
// Transformer block with RBF x spherical-harmonic relative-position encoding.
// R4->R5: FFN GEMMs rebuilt as 128x64-tile SGEMMs (8x4 microtile, double-
// buffered smem, 1 barrier/chunk). k_scores stages rel_diss/rel_dirs in smem.
// ---------------------------------------------------------------------------

#define CUTOFF  10.0f
#define NRAD    64
#define NSPH    9
#define NHEADS  8
#define DMODEL  512
#define DHEAD   64
#define SEQL    256
#define NB      2
#define NROWS   (NB*SEQL)      // 512
#define NF      (NRAD*NSPH)    // 576
#define DFF     2048
#define KSPLIT  4

// padded vw layout: h-stride 604 words (604 % 32 == 28 -> bank-staggered)
#define VW_H    604
#define VW_ROW  (NHEADS*VW_H)  // 4832 words per row
#define WS      260            // w_sm head stride

__device__ __align__(16) float g_vw[NROWS*VW_ROW];             // padded [row][h][f]
__device__ __align__(16) float g_cb[NROWS*NHEADS];
__device__ __align__(16) float g_base[NB*NHEADS*SEQL*SEQL];    // logits -> weights
__device__ __align__(16) float g_attn[NROWS*DMODEL];
__device__ __align__(16) float g_x1[NROWS*DMODEL];
__device__ __align__(16) float g_hid[NROWS*DFF];
__device__ __align__(16) float g_yp[KSPLIT*NROWS*DMODEL];

// ---------------------------------------------------------------------------
// K1: vw[row, h, f] = sum_dh src[row, h*64+dh] * rp_w[f, h*64+dh]  (padded out)
// ---------------------------------------------------------------------------
__global__ __launch_bounds__(256) void k_vw(const float* __restrict__ src,
                                            const float* __restrict__ rp_w) {
    __shared__ __align__(16) float As[64][64];   // [dh][row]
    __shared__ __align__(16) float Bs[64][64];   // [dh][f]
    const int f0   = blockIdx.x * 64;
    const int row0 = blockIdx.y * 64;
    const int h    = blockIdx.z;
    const int tid  = threadIdx.x;
#pragma unroll
    for (int i = 0; i < 4; i++) {
        int lin = i * 256 + tid;
        int r   = lin >> 4;
        int k4  = lin & 15;
        float4 a = *(const float4*)&src [(row0 + r) * DMODEL + h * DHEAD + k4 * 4];
        As[k4*4+0][r] = a.x; As[k4*4+1][r] = a.y; As[k4*4+2][r] = a.z; As[k4*4+3][r] = a.w;
        float4 b = *(const float4*)&rp_w[(f0   + r) * DMODEL + h * DHEAD + k4 * 4];
        Bs[k4*4+0][r] = b.x; Bs[k4*4+1][r] = b.y; Bs[k4*4+2][r] = b.z; Bs[k4*4+3][r] = b.w;
    }
    __syncthreads();
    const int tx = tid & 15, ty = tid >> 4;
    float acc[4][4] = {};
#pragma unroll
    for (int k = 0; k < 64; k++) {
        float a[4], b[4];
        *(float4*)a = *(const float4*)&As[k][ty * 4];
        *(float4*)b = *(const float4*)&Bs[k][tx * 4];
#pragma unroll
        for (int i = 0; i < 4; i++)
#pragma unroll
            for (int j = 0; j < 4; j++) acc[i][j] += a[i] * b[j];
    }
#pragma unroll
    for (int i = 0; i < 4; i++) {
        float4 o = make_float4(acc[i][0], acc[i][1], acc[i][2], acc[i][3]);
        *(float4*)&g_vw[(row0 + ty*4 + i) * VW_ROW + h * VW_H + f0 + tx * 4] = o;
    }
}

// ---------------------------------------------------------------------------
// K1b: cb[row,h] = sum_dh rp_b[h*64+dh]*src[row, h*64+dh]
// ---------------------------------------------------------------------------
__global__ void k_cb(const float* __restrict__ src, const float* __restrict__ rp_b) {
    int i = blockIdx.x * blockDim.x + threadIdx.x;
    if (i >= NROWS * NHEADS) return;
    int row = i >> 3, h = i & 7;
    const float* s  = &src[row * DMODEL + h * DHEAD];
    const float* bb = &rp_b[h * DHEAD];
    float acc = 0.0f;
#pragma unroll
    for (int k = 0; k < DHEAD; k++) acc += s[k] * bb[k];
    g_cb[i] = acc;
}

// ---------------------------------------------------------------------------
// K2: base[b,h,l,m] = (1/8) * sum_dh q[b,l,h,dh]*q[b,m,h,dh]
// ---------------------------------------------------------------------------
__global__ __launch_bounds__(256) void k_base(const float* __restrict__ src) {
    __shared__ __align__(16) float As[64][64];
    __shared__ __align__(16) float Bs[64][64];
    const int m0 = blockIdx.x * 64;
    const int l0 = blockIdx.y * 64;
    const int b  = blockIdx.z >> 3;
    const int h  = blockIdx.z & 7;
    const int tid = threadIdx.x;
    const float* sb = src + b * SEQL * DMODEL;
#pragma unroll
    for (int i = 0; i < 4; i++) {
        int lin = i * 256 + tid;
        int r   = lin >> 4;
        int k4  = lin & 15;
        float4 a = *(const float4*)&sb[(l0 + r) * DMODEL + h * DHEAD + k4 * 4];
        As[k4*4+0][r] = a.x; As[k4*4+1][r] = a.y; As[k4*4+2][r] = a.z; As[k4*4+3][r] = a.w;
        float4 c = *(const float4*)&sb[(m0 + r) * DMODEL + h * DHEAD + k4 * 4];
        Bs[k4*4+0][r] = c.x; Bs[k4*4+1][r] = c.y; Bs[k4*4+2][r] = c.z; Bs[k4*4+3][r] = c.w;
    }
    __syncthreads();
    const int tx = tid & 15, ty = tid >> 4;
    float acc[4][4] = {};
#pragma unroll
    for (int k = 0; k < 64; k++) {
        float a[4], c[4];
        *(float4*)a = *(const float4*)&As[k][ty * 4];
        *(float4*)c = *(const float4*)&Bs[k][tx * 4];
#pragma unroll
        for (int i = 0; i < 4; i++)
#pragma unroll
            for (int j = 0; j < 4; j++) acc[i][j] += a[i] * c[j];
    }
#pragma unroll
    for (int i = 0; i < 4; i++) {
        float4 o = make_float4(acc[i][0]*0.125f, acc[i][1]*0.125f,
                               acc[i][2]*0.125f, acc[i][3]*0.125f);
        *(float4*)&g_base[((b*NHEADS + h)*SEQL + l0 + ty*4 + i) * SEQL + m0 + tx*4] = o;
    }
}

// ---------------------------------------------------------------------------
// K3: scores + softmax. One warp per key m; lanes = (h, r-quad).
// rel data staged in smem; normalized weights written back into g_base.
// ---------------------------------------------------------------------------
__global__ __launch_bounds__(256, 3) void k_scores(
    const float* __restrict__ rel_diss, const float* __restrict__ rel_dirs) {
    __shared__ __align__(16) float vw_sm[VW_ROW];    // 19328 B
    __shared__ float w_sm[NHEADS * WS];              // 8320 B
    __shared__ float d_sm[SEQL];
    __shared__ float dir_sm[SEQL * 3];
    __shared__ float cb_sm[NHEADS];
    __shared__ float maxv[NHEADS], sumv[NHEADS];

    const int row = blockIdx.x;        // b*256 + l
    const int b   = row >> 8;
    const int l   = row & 255;
    const int tid = threadIdx.x;

    {   // stage padded vw row
        const float4* vs = (const float4*)&g_vw[row * VW_ROW];
        float4* vd = (float4*)vw_sm;
        for (int i = tid; i < VW_ROW / 4; i += 256) vd[i] = vs[i];
    }
    // stage base logits (coalesced) into w_sm
#pragma unroll
    for (int h = 0; h < NHEADS; h++)
        w_sm[h * WS + tid] = g_base[((b * NHEADS + h) * SEQL + l) * SEQL + tid];
    // stage rel data (coalesced)
    d_sm[tid] = rel_diss[row * SEQL + tid];
#pragma unroll
    for (int i = 0; i < 3; i++)
        dir_sm[i * 256 + tid] = rel_dirs[row * SEQL * 3 + i * 256 + tid];
    if (tid < NHEADS) cb_sm[tid] = g_cb[row * NHEADS + tid];
    __syncthreads();

    const int wrp = tid >> 5, lane = tid & 31;
    const int hh = lane & 7, rq = lane >> 3;
    const float inv2w2 = 20.48f;
    const float cstep  = CUTOFF / 63.0f;

    for (int i = 0; i < 32; i++) {
        const int m = i * 8 + wrp;
        const float d  = d_sm[m];
        const float dx = dir_sm[3 * m + 0];
        const float dy = dir_sm[3 * m + 1];
        const float dz = dir_sm[3 * m + 2];
        const float dc  = fminf(fmaxf(d * (1.0f / CUTOFF), 0.0f), 1.0f);
        const float env = 0.5f * (__cosf(3.14159265358979f * dc) + 1.0f);

        float sp[9];
        sp[0] = 0.28209479177387814f;
        sp[1] = 0.4886025119029199f * dy;
        sp[2] = 0.4886025119029199f * dz;
        sp[3] = 0.4886025119029199f * dx;
        sp[4] = 1.0925484305920792f * dx * dy;
        sp[5] = 1.0925484305920792f * dy * dz;
        sp[6] = 0.31539156525252005f * (3.0f * dz * dz - 1.0f);
        sp[7] = 1.0925484305920792f * dx * dz;
        sp[8] = 0.5462742152960396f * (dx * dx - dy * dy);

        int ic = (int)floorf(d * (63.0f / CUTOFF) + 0.5f);
        int r0 = (ic - 6) & ~3;
        r0 = min(max(r0, 0), NRAD - 16);
        const float base_d = d - (float)r0 * cstep;

        float ux = 0.0f, uy = 0.0f, uz = 0.0f, uw = 0.0f;
        const float* vp = &vw_sm[hh * VW_H + r0 + rq * 4];
#pragma unroll
        for (int s = 0; s < NSPH; s++) {
            float4 v = *(const float4*)&vp[s * NRAD];
            ux += sp[s] * v.x; uy += sp[s] * v.y;
            uz += sp[s] * v.z; uw += sp[s] * v.w;
        }
        float f0 = base_d - (float)(rq * 4 + 0) * cstep;
        float f1 = base_d - (float)(rq * 4 + 1) * cstep;
        float f2 = base_d - (float)(rq * 4 + 2) * cstep;
        float f3 = base_d - (float)(rq * 4 + 3) * cstep;
        float part = __expf(-f0 * f0 * inv2w2) * ux
                   + __expf(-f1 * f1 * inv2w2) * uy
                   + __expf(-f2 * f2 * inv2w2) * uz
                   + __expf(-f3 * f3 * inv2w2) * uw;
        part += __shfl_xor_sync(0xffffffffu, part, 8);
        part += __shfl_xor_sync(0xffffffffu, part, 16);
        if (rq == 0)
            w_sm[hh * WS + m] += env * part + cb_sm[hh];
    }
    __syncthreads();

    // softmax: warp wrp reduces head h=wrp
    {
        float mv = -1e30f;
#pragma unroll
        for (int i = 0; i < 8; i++) mv = fmaxf(mv, w_sm[wrp * WS + lane + i * 32]);
#pragma unroll
        for (int o = 16; o > 0; o >>= 1) mv = fmaxf(mv, __shfl_xor_sync(0xffffffffu, mv, o));
        if (lane == 0) maxv[wrp] = mv;
    }
    __syncthreads();
#pragma unroll
    for (int h = 0; h < NHEADS; h++)
        w_sm[h * WS + tid] = __expf(w_sm[h * WS + tid] - maxv[h]);
    __syncthreads();
    {
        float sv = 0.0f;
#pragma unroll
        for (int i = 0; i < 8; i++) sv += w_sm[wrp * WS + lane + i * 32];
#pragma unroll
        for (int o = 16; o > 0; o >>= 1) sv += __shfl_xor_sync(0xffffffffu, sv, o);
        if (lane == 0) sumv[wrp] = sv;
    }
    __syncthreads();
#pragma unroll
    for (int h = 0; h < NHEADS; h++) {
        float inv_s = 1.0f / sumv[h];
        g_base[((b * NHEADS + h) * SEQL + l) * SEQL + tid] = w_sm[h * WS + tid] * inv_s;
    }
}

// ---------------------------------------------------------------------------
// K3b: attn output = W @ V as tiled smem GEMM. grid (h, l-tile32, b).
// ---------------------------------------------------------------------------
__global__ __launch_bounds__(256) void k_av(const float* __restrict__ src) {
    __shared__ float Ws[32][33];       // [l][m]
    __shared__ float Vs[32][68];       // [m][dh]
    const int h  = blockIdx.x;
    const int l0 = blockIdx.y * 32;
    const int b  = blockIdx.z;
    const int tid = threadIdx.x;
    const int tx = tid & 15, ty = tid >> 4;        // ty 0..15
    const float* W = g_base + ((b * NHEADS + h) * SEQL) * SEQL;   // [l][m]
    const float* V = src + b * SEQL * DMODEL + h * DHEAD;         // [m][512]

    float acc[2][4] = {};
    for (int mc = 0; mc < 8; mc++) {
        const int m0 = mc * 32;
        {
            int r = tid >> 3, c = tid & 7;
            float4 wv = *(const float4*)&W[(l0 + r) * SEQL + m0 + c * 4];
            Ws[r][c*4+0] = wv.x; Ws[r][c*4+1] = wv.y;
            Ws[r][c*4+2] = wv.z; Ws[r][c*4+3] = wv.w;
            float4 v0 = *(const float4*)&V[(m0 + r) * DMODEL + c * 8];
            float4 v1 = *(const float4*)&V[(m0 + r) * DMODEL + c * 8 + 4];
            Vs[r][c*8+0] = v0.x; Vs[r][c*8+1] = v0.y;
            Vs[r][c*8+2] = v0.z; Vs[r][c*8+3] = v0.w;
            Vs[r][c*8+4] = v1.x; Vs[r][c*8+5] = v1.y;
            Vs[r][c*8+6] = v1.z; Vs[r][c*8+7] = v1.w;
        }
        __syncthreads();
#pragma unroll
        for (int k = 0; k < 32; k++) {
            float a0 = Ws[ty][k];
            float a1 = Ws[ty + 16][k];
            float4 bv = *(const float4*)&Vs[k][tx * 4];
            acc[0][0] += a0 * bv.x; acc[0][1] += a0 * bv.y;
            acc[0][2] += a0 * bv.z; acc[0][3] += a0 * bv.w;
            acc[1][0] += a1 * bv.x; acc[1][1] += a1 * bv.y;
            acc[1][2] += a1 * bv.z; acc[1][3] += a1 * bv.w;
        }
        __syncthreads();
    }
#pragma unroll
    for (int i = 0; i < 2; i++) {
        float4 o = make_float4(acc[i][0], acc[i][1], acc[i][2], acc[i][3]);
        *(float4*)&g_attn[(b * SEQL + l0 + ty + i * 16) * DMODEL + h * DHEAD + tx * 4] = o;
    }
}

// ---------------------------------------------------------------------------
// K3c: x = LN1(src + attn)
// ---------------------------------------------------------------------------
__global__ __launch_bounds__(256) void k_ln1(const float* __restrict__ src,
                                             const float* __restrict__ gamma1,
                                             const float* __restrict__ beta1) {
    __shared__ float redA[256], redB[256];
    const int row = blockIdx.x;
    const int tid = threadIdx.x;
    const int d0 = tid, d1 = tid + 256;
    float x0 = src[row * DMODEL + d0] + g_attn[row * DMODEL + d0];
    float x1 = src[row * DMODEL + d1] + g_attn[row * DMODEL + d1];
    redA[tid] = x0 + x1;
    redB[tid] = x0 * x0 + x1 * x1;
    __syncthreads();
    for (int st = 128; st > 0; st >>= 1) {
        if (tid < st) { redA[tid] += redA[tid + st]; redB[tid] += redB[tid + st]; }
        __syncthreads();
    }
    const float mu   = redA[0] * (1.0f / DMODEL);
    const float var  = redB[0] * (1.0f / DMODEL) - mu * mu;
    const float rstd = rsqrtf(var + 1e-5f);
    g_x1[row * DMODEL + d0] = (x0 - mu) * rstd * gamma1[d0] + beta1[d0];
    g_x1[row * DMODEL + d1] = (x1 - mu) * rstd * gamma1[d1] + beta1[d1];
}

// ---------------------------------------------------------------------------
// K4: FFN GEMM1  g_hid = leaky_relu(g_x1 @ w1 + b1)
// 128x64 tile, 8x4 microtile, double-buffered smem, 1 barrier/chunk.
// grid (DFF/64=32, NROWS/128=4)
// ---------------------------------------------------------------------------
__global__ __launch_bounds__(256) void k_gemm1(const float* __restrict__ w1,
                                               const float* __restrict__ b1) {
    __shared__ __align__(16) float As[2][16][128];   // [buf][k][row]
    __shared__ __align__(16) float Bs[2][16][64];    // [buf][k][col]
    const int col0 = blockIdx.x * 64;
    const int row0 = blockIdx.y * 128;
    const int tid  = threadIdx.x;
    const int tx = tid & 15, ty = tid >> 4;          // out: rows ty*8.., cols tx*4..
    const int ar = tid & 127, akg = tid >> 7;        // A loads: row ar, kg akg/akg+2
    const int bk = tid >> 4, bcg = tid & 15;         // B loads

    const float* Ap = &g_x1[(row0 + ar) * DMODEL];
    const float* Bp = &w1[col0 + bcg * 4];

    float4 pa0 = *(const float4*)&Ap[akg * 4];
    float4 pa1 = *(const float4*)&Ap[(akg + 2) * 4];
    float4 pb  = *(const float4*)&Bp[bk * DFF];
    As[0][akg*4+0][ar] = pa0.x; As[0][akg*4+1][ar] = pa0.y;
    As[0][akg*4+2][ar] = pa0.z; As[0][akg*4+3][ar] = pa0.w;
    As[0][akg*4+8][ar] = pa1.x; As[0][akg*4+9][ar] = pa1.y;
    As[0][akg*4+10][ar] = pa1.z; As[0][akg*4+11][ar] = pa1.w;
    *(float4*)&Bs[0][bk][bcg * 4] = pb;
    __syncthreads();

    float acc[8][4] = {};
    const int NC = DMODEL / 16;                      // 32
#pragma unroll 1
    for (int c = 0; c < NC; c++) {
        const int cur = c & 1;
        if (c + 1 < NC) {
            const int k0 = (c + 1) * 16;
            pa0 = *(const float4*)&Ap[k0 + akg * 4];
            pa1 = *(const float4*)&Ap[k0 + (akg + 2) * 4];
            pb  = *(const float4*)&Bp[(k0 + bk) * DFF];
        }
#pragma unroll
        for (int k = 0; k < 16; k++) {
            float a[8], bb[4];
            *(float4*)&a[0] = *(const float4*)&As[cur][k][ty * 8];
            *(float4*)&a[4] = *(const float4*)&As[cur][k][ty * 8 + 4];
            *(float4*)&bb[0] = *(const float4*)&Bs[cur][k][tx * 4];
#pragma unroll
            for (int i = 0; i < 8; i++)
#pragma unroll
                for (int j = 0; j < 4; j++) acc[i][j] += a[i] * bb[j];
        }
        if (c + 1 < NC) {
            const int nxt = cur ^ 1;
            As[nxt][akg*4+0][ar] = pa0.x; As[nxt][akg*4+1][ar] = pa0.y;
            As[nxt][akg*4+2][ar] = pa0.z; As[nxt][akg*4+3][ar] = pa0.w;
            As[nxt][akg*4+8][ar] = pa1.x; As[nxt][akg*4+9][ar] = pa1.y;
            As[nxt][akg*4+10][ar] = pa1.z; As[nxt][akg*4+11][ar] = pa1.w;
            *(float4*)&Bs[nxt][bk][bcg * 4] = pb;
        }
        __syncthreads();
    }

    float4 bv = *(const float4*)&b1[col0 + tx * 4];
#pragma unroll
    for (int i = 0; i < 8; i++) {
        float v0 = acc[i][0] + bv.x;
        float v1 = acc[i][1] + bv.y;
        float v2 = acc[i][2] + bv.z;
        float v3 = acc[i][3] + bv.w;
        float4 o;
        o.x = v0 > 0.0f ? v0 : 0.01f * v0;
        o.y = v1 > 0.0f ? v1 : 0.01f * v1;
        o.z = v2 > 0.0f ? v2 : 0.01f * v2;
        o.w = v3 > 0.0f ? v3 : 0.01f * v3;
        *(float4*)&g_hid[(row0 + ty * 8 + i) * DFF + col0 + tx * 4] = o;
    }
}

// ---------------------------------------------------------------------------
// K5: FFN GEMM2 (split-K=4 deterministic partials), same tiling as gemm1.
// grid (DMODEL/64=8, NROWS/128=4, KSPLIT=4)
// ---------------------------------------------------------------------------
__global__ __launch_bounds__(256) void k_gemm2(const float* __restrict__ w2) {
    __shared__ __align__(16) float As[2][16][128];
    __shared__ __align__(16) float Bs[2][16][64];
    const int col0 = blockIdx.x * 64;
    const int row0 = blockIdx.y * 128;
    const int kz   = blockIdx.z;
    const int tid  = threadIdx.x;
    const int tx = tid & 15, ty = tid >> 4;
    const int ar = tid & 127, akg = tid >> 7;
    const int bk = tid >> 4, bcg = tid & 15;
    const int kbeg = kz * (DFF / KSPLIT);            // 512-wide slice

    const float* Ap = &g_hid[(row0 + ar) * DFF + kbeg];
    const float* Bp = &w2[kbeg * DMODEL + col0 + bcg * 4];

    float4 pa0 = *(const float4*)&Ap[akg * 4];
    float4 pa1 = *(const float4*)&Ap[(akg + 2) * 4];
    float4 pb  = *(const float4*)&Bp[bk * DMODEL];
    As[0][akg*4+0][ar] = pa0.x; As[0][akg*4+1][ar] = pa0.y;
    As[0][akg*4+2][ar] = pa0.z; As[0][akg*4+3][ar] = pa0.w;
    As[0][akg*4+8][ar] = pa1.x; As[0][akg*4+9][ar] = pa1.y;
    As[0][akg*4+10][ar] = pa1.z; As[0][akg*4+11][ar] = pa1.w;
    *(float4*)&Bs[0][bk][bcg * 4] = pb;
    __syncthreads();

    float acc[8][4] = {};
    const int NC = (DFF / KSPLIT) / 16;              // 32
#pragma unroll 1
    for (int c = 0; c < NC; c++) {
        const int cur = c & 1;
        if (c + 1 < NC) {
            const int k0 = (c + 1) * 16;
            pa0 = *(const float4*)&Ap[k0 + akg * 4];
            pa1 = *(const float4*)&Ap[k0 + (akg + 2) * 4];
            pb  = *(const float4*)&Bp[(k0 + bk) * DMODEL];
        }
#pragma unroll
        for (int k = 0; k < 16; k++) {
            float a[8], bb[4];
            *(float4*)&a[0] = *(const float4*)&As[cur][k][ty * 8];
            *(float4*)&a[4] = *(const float4*)&As[cur][k][ty * 8 + 4];
            *(float4*)&bb[0] = *(const float4*)&Bs[cur][k][tx * 4];
#pragma unroll
            for (int i = 0; i < 8; i++)
#pragma unroll
                for (int j = 0; j < 4; j++) acc[i][j] += a[i] * bb[j];
        }
        if (c + 1 < NC) {
            const int nxt = cur ^ 1;
            As[nxt][akg*4+0][ar] = pa0.x; As[nxt][akg*4+1][ar] = pa0.y;
            As[nxt][akg*4+2][ar] = pa0.z; As[nxt][akg*4+3][ar] = pa0.w;
            As[nxt][akg*4+8][ar] = pa1.x; As[nxt][akg*4+9][ar] = pa1.y;
            As[nxt][akg*4+10][ar] = pa1.z; As[nxt][akg*4+11][ar] = pa1.w;
            *(float4*)&Bs[nxt][bk][bcg * 4] = pb;
        }
        __syncthreads();
    }

#pragma unroll
    for (int i = 0; i < 8; i++) {
        float4 o = make_float4(acc[i][0], acc[i][1], acc[i][2], acc[i][3]);
        *(float4*)&g_yp[kz * NROWS * DMODEL + (row0 + ty * 8 + i) * DMODEL + col0 + tx * 4] = o;
    }
}

// ---------------------------------------------------------------------------
// K6: combine split-K partials + b2 + residual(x) -> LN2 -> out
// ---------------------------------------------------------------------------
__global__ __launch_bounds__(256) void k_ln2(const float* __restrict__ b2,
                                             const float* __restrict__ gamma2,
                                             const float* __restrict__ beta2,
                                             float* __restrict__ out) {
    __shared__ float redA[256], redB[256];
    const int row = blockIdx.x;
    const int tid = threadIdx.x;
    const int d0 = tid, d1 = tid + 256;
    float y0 = g_x1[row * DMODEL + d0] + b2[d0];
    float y1 = g_x1[row * DMODEL + d1] + b2[d1];
#pragma unroll
    for (int kz = 0; kz < KSPLIT; kz++) {
        y0 += g_yp[kz * NROWS * DMODEL + row * DMODEL + d0];
        y1 += g_yp[kz * NROWS * DMODEL + row * DMODEL + d1];
    }
    redA[tid] = y0 + y1;
    redB[tid] = y0 * y0 + y1 * y1;
    __syncthreads();
    for (int st = 128; st > 0; st >>= 1) {
        if (tid < st) { redA[tid] += redA[tid + st]; redB[tid] += redB[tid + st]; }
        __syncthreads();
    }
    const float mu   = redA[0] * (1.0f / DMODEL);
    const float var  = redB[0] * (1.0f / DMODEL) - mu * mu;
    const float rstd = rsqrtf(var + 1e-5f);
    out[row * DMODEL + d0] = (y0 - mu) * rstd * gamma2[d0] + beta2[d0];
    out[row * DMODEL + d1] = (y1 - mu) * rstd * gamma2[d1] + beta2[d1];
}

// ---------------------------------------------------------------------------
extern "C" void kernel_launch(void* const* d_in, const int* in_sizes, int n_in,
                              void* d_out, int out_size) {
    (void)in_sizes; (void)n_in; (void)out_size;
    const float* src      = (const float*)d_in[0];
    const float* rel_diss = (const float*)d_in[1];
    const float* rel_dirs = (const float*)d_in[2];
    const float* rp_w     = (const float*)d_in[3];
    const float* rp_b     = (const float*)d_in[4];
    const float* w1       = (const float*)d_in[5];
    const float* b1       = (const float*)d_in[6];
    const float* w2       = (const float*)d_in[7];
    const float* b2       = (const float*)d_in[8];
    const float* gamma1   = (const float*)d_in[9];
    const float* beta1    = (const float*)d_in[10];
    const float* gamma2   = (const float*)d_in[11];
    const float* beta2    = (const float*)d_in[12];
    float* out = (float*)d_out;

    k_vw    <<<dim3(NF/64, NROWS/64, NHEADS), 256>>>(src, rp_w);
    k_cb    <<<(NROWS*NHEADS + 255)/256, 256>>>(src, rp_b);
    k_base  <<<dim3(SEQL/64, SEQL/64, NB*NHEADS), 256>>>(src);
    k_scores<<<NROWS, 256>>>(rel_diss, rel_dirs);
    k_av    <<<dim3(NHEADS, SEQL/32, NB), 256>>>(src);
    k_ln1   <<<NROWS, 256>>>(src, gamma1, beta1);
    k_gemm1 <<<dim3(DFF/64, NROWS/128), 256>>>(w1, b1);
    k_gemm2 <<<dim3(DMODEL/64, NROWS/128, KSPLIT), 256>>>(w2);
    k_ln2   <<<NROWS, 256>>>(b2, gamma2, beta2, out);
}